// round 9
// baseline (speedup 1.0000x reference)
#include <cuda_runtime.h>
#include <math.h>
#include <stdint.h>

// Problem dims
#define MROWS   8192      // B*T
#define DMODEL  1024
#define DQKVG   4096
#define NHEADS  16
#define DHEAD   64
#define TLEN    2048
#define BATCHSZ 4
#define CHUNK   64
#define NCHUNK  (TLEN / CHUNK)   // 32

// mma.sync tf32 GEMM tiling
#define KDIM    1024
#define BK      32
#define NKCH    (KDIM / BK)      // 32
#define ASTRIDE 36               // padded row stride (floats) -> conflict-free frags
#define NSTAGE  3

// Scratch (device globals — allocation-free per harness rules)
__device__ __align__(256) float g_xn[(size_t)MROWS * DMODEL];
__device__ __align__(256) float g_qkvg[(size_t)MROWS * DQKVG];
__device__ __align__(256) float g_og[(size_t)MROWS * DMODEL];
__device__ __align__(256) float g_chunkS[(size_t)BATCHSZ * NHEADS * NCHUNK * 64 * 64];
__device__ __align__(256) float g_state [(size_t)BATCHSZ * NHEADS * NCHUNK * 64 * 64];
// tf32-pre-rounded weights: [WQ;WK;WV;Wg] and WO
__device__ __align__(256) float g_wt [(size_t)DQKVG * KDIM];
__device__ __align__(256) float g_wot[(size_t)DMODEL * KDIM];

// ---------------------------------------------------------------------------
// helpers
// ---------------------------------------------------------------------------
__device__ __forceinline__ uint32_t f2tf32(float x) {
    uint32_t y;
    asm("cvt.rna.tf32.f32 %0, %1;" : "=r"(y) : "f"(x));
    return y;
}
__device__ __forceinline__ float f2tf32f(float x) {
    return __uint_as_float(f2tf32(x));
}
__device__ __forceinline__ uint32_t smem_u32(const void* p) {
    uint32_t a;
    asm("{ .reg .u64 t; cvta.to.shared.u64 t, %1; cvt.u32.u64 %0, t; }" : "=r"(a) : "l"(p));
    return a;
}
__device__ __forceinline__ void mma_tf32(float* d, const uint32_t* a, const uint32_t* b) {
    asm volatile(
        "mma.sync.aligned.m16n8k8.row.col.f32.tf32.tf32.f32 "
        "{%0,%1,%2,%3}, {%4,%5,%6,%7}, {%8,%9}, {%0,%1,%2,%3};\n"
        : "+f"(d[0]), "+f"(d[1]), "+f"(d[2]), "+f"(d[3])
        : "r"(a[0]), "r"(a[1]), "r"(a[2]), "r"(a[3]), "r"(b[0]), "r"(b[1]));
}
#define CP_ASYNC16(dst, src) \
    asm volatile("cp.async.cg.shared.global [%0], [%1], 16;\n" :: "r"(dst), "l"(src))
#define CP_COMMIT() asm volatile("cp.async.commit_group;\n" ::: "memory")
#define CP_WAIT2()  asm volatile("cp.async.wait_group 2;\n" ::: "memory")

// Geometry parametrized on NT (n-tiles of 8 per warp): BN = 32*NT
template<int NT> struct GP {
    static constexpr int BN     = NT * 32;
    static constexpr int ABUFW  = 128 * ASTRIDE;          // A words per stage
    static constexpr int BBUFW  = BN * ASTRIDE;           // B words per stage
    static constexpr int STAGEW = ABUFW + BBUFW;
    static constexpr int SMEMB  = NSTAGE * STAGEW * 4;
};

template<int NT>
__device__ __forceinline__ void issue_stage(const float* __restrict__ Ag,
                                            const float* __restrict__ Bg,
                                            uint32_t sbase, int stage, int k0,
                                            int tid) {
    uint32_t As = sbase + stage * (GP<NT>::STAGEW * 4);
    uint32_t Bs = As + GP<NT>::ABUFW * 4;
    int r0 = tid >> 3, c4 = (tid & 7) * 4;
    #pragma unroll
    for (int i = 0; i < 4; i++) {
        int r = r0 + 32 * i;
        CP_ASYNC16(As + (r * ASTRIDE + c4) * 4, Ag + (size_t)r * KDIM + k0 + c4);
    }
    #pragma unroll
    for (int i = 0; i < GP<NT>::BN / 32; i++) {
        int r = r0 + 32 * i;
        CP_ASYNC16(Bs + (r * ASTRIDE + c4) * 4, Bg + (size_t)r * KDIM + k0 + c4);
    }
}

template<int NT>
__device__ __forceinline__ void s_compute(const uint32_t* __restrict__ sm, int buf,
                                          int lane, int wm, int wn,
                                          float acc[4][NT][4]) {
    const uint32_t* As = sm + buf * GP<NT>::STAGEW;
    const uint32_t* Bs = As + GP<NT>::ABUFW;
    int mbase = wm * 64 + (lane >> 2);
    int nbase = wn * (NT * 8) + (lane >> 2);
    int kq = lane & 3;
    #pragma unroll
    for (int kk = 0; kk < 4; kk++) {
        int k0 = kk * 8 + kq;
        uint32_t a[4][4], b[NT][2];
        #pragma unroll
        for (int mt = 0; mt < 4; mt++) {
            a[mt][0] = As[(mbase + mt * 16    ) * ASTRIDE + k0];
            a[mt][1] = As[(mbase + mt * 16 + 8) * ASTRIDE + k0];
            a[mt][2] = As[(mbase + mt * 16    ) * ASTRIDE + k0 + 4];
            a[mt][3] = As[(mbase + mt * 16 + 8) * ASTRIDE + k0 + 4];
        }
        #pragma unroll
        for (int nt = 0; nt < NT; nt++) {
            b[nt][0] = Bs[(nbase + nt * 8) * ASTRIDE + k0];
            b[nt][1] = Bs[(nbase + nt * 8) * ASTRIDE + k0 + 4];
        }
        #pragma unroll
        for (int mt = 0; mt < 4; mt++)
            #pragma unroll
            for (int nt = 0; nt < NT; nt++)
                mma_tf32(acc[mt][nt], a[mt], b[nt]);
    }
}

// full mainloop: acc = A[128xK] * B[BNxK]^T, 3-stage cp.async pipeline
template<int NT>
__device__ __forceinline__ void tf32_mainloop(const float* __restrict__ Ag,
                                              const float* __restrict__ Bg,
                                              uint32_t* sm, int tid,
                                              float acc[4][NT][4]) {
    int lane = tid & 31, warp = tid >> 5;
    int wm = warp & 1, wn = warp >> 1;
    uint32_t sb = smem_u32(sm);

    issue_stage<NT>(Ag, Bg, sb, 0, 0, tid);    CP_COMMIT();
    issue_stage<NT>(Ag, Bg, sb, 1, BK, tid);   CP_COMMIT();

    #pragma unroll 1
    for (int c = 0; c < NKCH; c++) {
        if (c + 2 < NKCH) {
            int st = c + 2;
            issue_stage<NT>(Ag, Bg, sb, st % NSTAGE, st * BK, tid);
        }
        CP_COMMIT();
        CP_WAIT2();
        __syncthreads();
        s_compute<NT>(sm, c % NSTAGE, lane, wm, wn, acc);
        __syncthreads();
    }
}

// ---------------------------------------------------------------------------
// GEMM 1: g_qkvg = g_xn @ g_wt^T + bias (+silu on G block)
// BM=128, BN=256; grid = (16, 64), 256 threads, 1 CTA/SM
// ---------------------------------------------------------------------------
__global__ __launch_bounds__(256, 1)
void tc_gemm_qkvg(const float* __restrict__ bQ, const float* __restrict__ bK,
                  const float* __restrict__ bV, const float* __restrict__ bg) {
    extern __shared__ uint32_t sm[];
    const int NT = 8;
    int tid = threadIdx.x;
    int lane = tid & 31, warp = tid >> 5;
    int wm = warp & 1, wn = warp >> 1;
    int bn = blockIdx.x, bm = blockIdx.y;

    int cb = bn * 256;
    int which = cb >> 10;                 // 256-col tile lies within one matrix
    const float* bias;
    if      (which == 0) bias = bQ;
    else if (which == 1) bias = bK;
    else if (which == 2) bias = bV;
    else                 bias = bg;
    const float* Bg = g_wt + (size_t)cb * KDIM;
    const float* Ag = g_xn + (size_t)(bm * 128) * KDIM;

    float acc[4][NT][4];
    #pragma unroll
    for (int i = 0; i < 4; i++)
        #pragma unroll
        for (int j = 0; j < NT; j++)
            #pragma unroll
            for (int k = 0; k < 4; k++) acc[i][j][k] = 0.f;

    tf32_mainloop<NT>(Ag, Bg, sm, tid, acc);

    bool do_silu = (which == 3);
    int row0 = bm * 128 + wm * 64 + (lane >> 2);
    int col0 = cb + wn * (NT * 8) + (lane & 3) * 2;
    #pragma unroll
    for (int mt = 0; mt < 4; mt++) {
        #pragma unroll
        for (int nt = 0; nt < NT; nt++) {
            int cg = col0 + nt * 8;
            float b0 = bias[cg & 1023], b1 = bias[(cg + 1) & 1023];
            #pragma unroll
            for (int half = 0; half < 2; half++) {
                size_t row = (size_t)(row0 + mt * 16 + half * 8);
                float v0 = acc[mt][nt][half * 2 + 0] + b0;
                float v1 = acc[mt][nt][half * 2 + 1] + b1;
                if (do_silu) {
                    v0 = v0 / (1.0f + expf(-v0));
                    v1 = v1 / (1.0f + expf(-v1));
                }
                *(float2*)(g_qkvg + row * DQKVG + cg) = make_float2(v0, v1);
            }
        }
    }
}

// ---------------------------------------------------------------------------
// GEMM 2: out = g_og @ g_wot^T + bO + x   BM=128, BN=128; grid = (8, 64)
// ---------------------------------------------------------------------------
__global__ __launch_bounds__(256, 2)
void tc_gemm_out(const float* __restrict__ bO,
                 const float* __restrict__ x, float* __restrict__ out) {
    extern __shared__ uint32_t sm[];
    const int NT = 4;
    int tid = threadIdx.x;
    int lane = tid & 31, warp = tid >> 5;
    int wm = warp & 1, wn = warp >> 1;
    int bn = blockIdx.x, bm = blockIdx.y;

    int cb = bn * 128;
    const float* Bg = g_wot + (size_t)cb * KDIM;
    const float* Ag = g_og + (size_t)(bm * 128) * KDIM;

    float acc[4][NT][4];
    #pragma unroll
    for (int i = 0; i < 4; i++)
        #pragma unroll
        for (int j = 0; j < NT; j++)
            #pragma unroll
            for (int k = 0; k < 4; k++) acc[i][j][k] = 0.f;

    tf32_mainloop<NT>(Ag, Bg, sm, tid, acc);

    int row0 = bm * 128 + wm * 64 + (lane >> 2);
    int col0 = cb + wn * 32 + (lane & 3) * 2;
    #pragma unroll
    for (int mt = 0; mt < 4; mt++) {
        #pragma unroll
        for (int nt = 0; nt < NT; nt++) {
            int cg = col0 + nt * 8;
            float b0 = bO[cg], b1 = bO[cg + 1];
            #pragma unroll
            for (int half = 0; half < 2; half++) {
                size_t row = (size_t)(row0 + mt * 16 + half * 8);
                float2 xr = *(const float2*)(x + row * DMODEL + cg);
                float2 v;
                v.x = acc[mt][nt][half * 2 + 0] + b0 + xr.x;
                v.y = acc[mt][nt][half * 2 + 1] + b1 + xr.y;
                *(float2*)(out + row * DMODEL + cg) = v;
            }
        }
    }
}

// ---------------------------------------------------------------------------
// prep: fused LayerNorm (blocks 0..8191) + weight tf32 pre-round (8192..13311)
// ---------------------------------------------------------------------------
__global__ __launch_bounds__(256) void prep_kernel(
    const float* __restrict__ x,
    const float* __restrict__ gamma, const float* __restrict__ beta,
    const float* __restrict__ WQ, const float* __restrict__ WK,
    const float* __restrict__ WV, const float* __restrict__ Wg,
    const float* __restrict__ WO) {
    int blk = blockIdx.x;
    int t = threadIdx.x;
    if (blk < MROWS) {
        // LayerNorm row, output tf32-pre-rounded
        const float4* xr = (const float4*)(x + (size_t)blk * DMODEL);
        float4 a = xr[t];
        float s = a.x + a.y + a.z + a.w;
        float q = a.x * a.x + a.y * a.y + a.z * a.z + a.w * a.w;
        #pragma unroll
        for (int o = 16; o > 0; o >>= 1) {
            s += __shfl_xor_sync(0xffffffffu, s, o);
            q += __shfl_xor_sync(0xffffffffu, q, o);
        }
        __shared__ float ss[8], sq[8];
        int w = t >> 5, lane = t & 31;
        if (lane == 0) { ss[w] = s; sq[w] = q; }
        __syncthreads();
        float st = 0.f, qt = 0.f;
        #pragma unroll
        for (int i = 0; i < 8; i++) { st += ss[i]; qt += sq[i]; }
        float mu = st * (1.0f / DMODEL);
        float var = qt * (1.0f / DMODEL) - mu * mu;
        float rs = rsqrtf(var + 1e-5f);
        float4 gm = ((const float4*)gamma)[t];
        float4 bt = ((const float4*)beta)[t];
        float4 o;
        o.x = f2tf32f((a.x - mu) * rs * gm.x + bt.x);
        o.y = f2tf32f((a.y - mu) * rs * gm.y + bt.y);
        o.z = f2tf32f((a.z - mu) * rs * gm.z + bt.z);
        o.w = f2tf32f((a.w - mu) * rs * gm.w + bt.w);
        ((float4*)(g_xn + (size_t)blk * DMODEL))[t] = o;
    } else {
        // weight conversion chunk
        int i = (blk - MROWS) * 256 + t;           // float4 index, < 1310720
        const float* src;
        float* dst;
        if (i < 1048576) {
            int m = i >> 18;
            int li = i & 262143;
            src = (m == 0 ? WQ : m == 1 ? WK : m == 2 ? WV : Wg) + (size_t)li * 4;
            dst = g_wt + (size_t)i * 4;
        } else {
            int li = i - 1048576;
            src = WO + (size_t)li * 4;
            dst = g_wot + (size_t)li * 4;
        }
        float4 v = *(const float4*)src;
        v.x = f2tf32f(v.x); v.y = f2tf32f(v.y);
        v.z = f2tf32f(v.z); v.w = f2tf32f(v.w);
        *(float4*)dst = v;
    }
}

// ---------------------------------------------------------------------------
// Pass 1: per-chunk state summary (unchanged)
// ---------------------------------------------------------------------------
__global__ __launch_bounds__(256) void chunk_summary(const float* __restrict__ alpha_logit) {
    int c = blockIdx.x & (NCHUNK - 1);
    int h = (blockIdx.x >> 5) & (NHEADS - 1);
    int b = blockIdx.x >> 9;

    __shared__ float Kt[64][65];
    __shared__ float Vs[64][65];
    __shared__ float lal[64];

    int tid = threadIdx.x;
    int tx = tid & 15, ty = tid >> 4;

    if (tid < 64) {
        float a = 1.0f / (1.0f + expf(-alpha_logit[h * 64 + tid]));
        lal[tid] = log2f(a);
    }
    __syncthreads();

    const float* rowb = g_qkvg + ((size_t)(b * TLEN + c * CHUNK)) * DQKVG + h * 64;
    #pragma unroll
    for (int i = 0; i < 4; i++) {
        int idx = tid + i * 256;
        int u = idx >> 4;
        int s4 = (idx & 15) << 2;
        const float* r = rowb + (size_t)u * DQKVG;
        float4 kv = *(const float4*)(r + 1024 + s4);
        float4 vv = *(const float4*)(r + 2048 + s4);
        float e = (float)(63 - u);
        Kt[u][s4 + 0] = kv.x * exp2f(lal[s4 + 0] * e);
        Kt[u][s4 + 1] = kv.y * exp2f(lal[s4 + 1] * e);
        Kt[u][s4 + 2] = kv.z * exp2f(lal[s4 + 2] * e);
        Kt[u][s4 + 3] = kv.w * exp2f(lal[s4 + 3] * e);
        Vs[u][s4 + 0] = vv.x;
        Vs[u][s4 + 1] = vv.y;
        Vs[u][s4 + 2] = vv.z;
        Vs[u][s4 + 3] = vv.w;
    }
    __syncthreads();

    float acc[4][4];
    #pragma unroll
    for (int i = 0; i < 4; i++)
        #pragma unroll
        for (int j = 0; j < 4; j++) acc[i][j] = 0.f;

    #pragma unroll 8
    for (int u = 0; u < 64; u++) {
        float ra[4], rb[4];
        #pragma unroll
        for (int i = 0; i < 4; i++) {
            ra[i] = Kt[u][ty * 4 + i];
            rb[i] = Vs[u][tx * 4 + i];
        }
        #pragma unroll
        for (int i = 0; i < 4; i++)
            #pragma unroll
            for (int j = 0; j < 4; j++)
                acc[i][j] = fmaf(ra[i], rb[j], acc[i][j]);
    }

    size_t ob = ((size_t)((b * NHEADS + h) * NCHUNK + c)) * 4096;
    #pragma unroll
    for (int i = 0; i < 4; i++)
        #pragma unroll
        for (int j = 0; j < 4; j++)
            g_chunkS[ob + (ty * 4 + i) * 64 + tx * 4 + j] = acc[i][j];
}

// ---------------------------------------------------------------------------
// Pass 2: sequential combine (unchanged)
// ---------------------------------------------------------------------------
__global__ __launch_bounds__(256) void chunk_combine(const float* __restrict__ alpha_logit) {
    int bh = blockIdx.x;
    int h = bh & (NHEADS - 1);
    int tid = threadIdx.x;

    float4 H[4];
    float aL[4];
    #pragma unroll
    for (int k = 0; k < 4; k++) {
        H[k] = make_float4(0.f, 0.f, 0.f, 0.f);
        int s = (tid + k * 256) >> 4;
        float a = 1.0f / (1.0f + expf(-alpha_logit[h * 64 + s]));
        aL[k] = exp2f(log2f(a) * 64.0f);
    }

    for (int c = 0; c < NCHUNK; c++) {
        size_t base = ((size_t)bh * NCHUNK + c) * 4096;
        #pragma unroll
        for (int k = 0; k < 4; k++) {
            int idx4 = tid + k * 256;
            ((float4*)(g_state + base))[idx4] = H[k];
            float4 S = ((const float4*)(g_chunkS + base))[idx4];
            H[k].x = aL[k] * H[k].x + S.x;
            H[k].y = aL[k] * H[k].y + S.y;
            H[k].z = aL[k] * H[k].z + S.z;
            H[k].w = aL[k] * H[k].w + S.w;
        }
    }
}

// ---------------------------------------------------------------------------
// Pass 3: intra-chunk output; epilogue writes tf32-pre-rounded g_og
// ---------------------------------------------------------------------------
__global__ __launch_bounds__(256) void chunk_output(const float* __restrict__ alpha_logit) {
    extern __shared__ float smf[];
    float (*Qt)[65] = (float(*)[65])(smf);
    float (*Ks)[65] = (float(*)[65])(smf + 4160);
    float (*Ms)[65] = (float(*)[65])(smf + 8320);
    float (*NN)[65] = (float(*)[65])(smf + 16640);

    __shared__ float al[64], lal[64];

    int c = blockIdx.x & (NCHUNK - 1);
    int h = (blockIdx.x >> 5) & (NHEADS - 1);
    int b = blockIdx.x >> 9;

    int tid = threadIdx.x;
    int tx = tid & 15, ty = tid >> 4;

    if (tid < 64) {
        float a = 1.0f / (1.0f + expf(-alpha_logit[h * 64 + tid]));
        al[tid] = a;
        lal[tid] = log2f(a);
    }
    __syncthreads();

    const float* rowb = g_qkvg + ((size_t)(b * TLEN + c * CHUNK)) * DQKVG + h * 64;
    size_t sbase = ((size_t)((b * NHEADS + h) * NCHUNK + c)) * 4096;

    #pragma unroll
    for (int i = 0; i < 4; i++) {
        int idx = tid + i * 256;
        int t = idx >> 4;
        int s4 = (idx & 15) << 2;
        const float* r = rowb + (size_t)t * DQKVG;
        float4 qv = *(const float4*)(r + s4);
        float4 kv = *(const float4*)(r + 1024 + s4);
        float4 vv = *(const float4*)(r + 2048 + s4);
        float tf = (float)t;
        Qt[s4 + 0][t] = qv.x * exp2f(lal[s4 + 0] * tf);
        Qt[s4 + 1][t] = qv.y * exp2f(lal[s4 + 1] * tf);
        Qt[s4 + 2][t] = qv.z * exp2f(lal[s4 + 2] * tf);
        Qt[s4 + 3][t] = qv.w * exp2f(lal[s4 + 3] * tf);
        Ks[s4 + 0][t] = kv.x * exp2f(-lal[s4 + 0] * tf);
        Ks[s4 + 1][t] = kv.y * exp2f(-lal[s4 + 1] * tf);
        Ks[s4 + 2][t] = kv.z * exp2f(-lal[s4 + 2] * tf);
        Ks[s4 + 3][t] = kv.w * exp2f(-lal[s4 + 3] * tf);
        NN[t][s4 + 0] = vv.x;
        NN[t][s4 + 1] = vv.y;
        NN[t][s4 + 2] = vv.z;
        NN[t][s4 + 3] = vv.w;
        float4 hv = *(const float4*)(g_state + sbase + (size_t)idx * 4);
        NN[64 + t][s4 + 0] = hv.x;
        NN[64 + t][s4 + 1] = hv.y;
        NN[64 + t][s4 + 2] = hv.z;
        NN[64 + t][s4 + 3] = hv.w;
    }
    __syncthreads();

    float acc[4][4];
    #pragma unroll
    for (int i = 0; i < 4; i++)
        #pragma unroll
        for (int j = 0; j < 4; j++) acc[i][j] = 0.f;

    #pragma unroll 8
    for (int s = 0; s < 64; s++) {
        float ra[4], rb[4];
        #pragma unroll
        for (int i = 0; i < 4; i++) {
            ra[i] = Qt[s][ty * 4 + i];
            rb[i] = Ks[s][tx * 4 + i];
        }
        #pragma unroll
        for (int i = 0; i < 4; i++)
            #pragma unroll
            for (int j = 0; j < 4; j++)
                acc[i][j] = fmaf(ra[i], rb[j], acc[i][j]);
    }

    #pragma unroll
    for (int i = 0; i < 4; i++) {
        int t = ty * 4 + i;
        #pragma unroll
        for (int j = 0; j < 4; j++) {
            int u = tx * 4 + j;
            Ms[u][t] = (u <= t) ? acc[i][j] : 0.f;
        }
    }
    #pragma unroll
    for (int i = 0; i < 4; i++) {
        int idx = tid + i * 256;
        int s = idx >> 4;
        int t4 = (idx & 15) << 2;
        float a = al[s];
        #pragma unroll
        for (int j = 0; j < 4; j++)
            Ms[64 + s][t4 + j] = Qt[s][t4 + j] * a;
    }
    __syncthreads();

    float o[4][4];
    #pragma unroll
    for (int i = 0; i < 4; i++)
        #pragma unroll
        for (int j = 0; j < 4; j++) o[i][j] = 0.f;

    #pragma unroll 8
    for (int jj = 0; jj < 128; jj++) {
        float ra[4], rb[4];
        #pragma unroll
        for (int i = 0; i < 4; i++) {
            ra[i] = Ms[jj][ty * 4 + i];
            rb[i] = NN[jj][tx * 4 + i];
        }
        #pragma unroll
        for (int i = 0; i < 4; i++)
            #pragma unroll
            for (int j = 0; j < 4; j++)
                o[i][j] = fmaf(ra[i], rb[j], o[i][j]);
    }

    float* ogb = g_og + ((size_t)(b * TLEN + c * CHUNK)) * DMODEL + h * 64;
    #pragma unroll
    for (int i = 0; i < 4; i++) {
        int t = ty * 4 + i;
        const float* gr = rowb + (size_t)t * DQKVG + 3072 + tx * 4;
        float4 g = *(const float4*)gr;
        float4 ov;
        ov.x = f2tf32f(o[i][0] * g.x);
        ov.y = f2tf32f(o[i][1] * g.y);
        ov.z = f2tf32f(o[i][2] * g.z);
        ov.w = f2tf32f(o[i][3] * g.w);
        *(float4*)(ogb + (size_t)t * DMODEL + tx * 4) = ov;
    }
}

// ---------------------------------------------------------------------------
extern "C" void kernel_launch(void* const* d_in, const int* in_sizes, int n_in,
                              void* d_out, int out_size) {
    const float* x      = (const float*)d_in[0];
    const float* WQ     = (const float*)d_in[1];
    const float* bQ     = (const float*)d_in[2];
    const float* WK     = (const float*)d_in[3];
    const float* bK     = (const float*)d_in[4];
    const float* WV     = (const float*)d_in[5];
    const float* bV     = (const float*)d_in[6];
    const float* WO     = (const float*)d_in[7];
    const float* bO     = (const float*)d_in[8];
    const float* Wg     = (const float*)d_in[9];
    const float* bg     = (const float*)d_in[10];
    const float* alpha  = (const float*)d_in[11];
    const float* gamma  = (const float*)d_in[12];
    const float* beta   = (const float*)d_in[13];
    float* out = (float*)d_out;

    cudaFuncSetAttribute(chunk_output, cudaFuncAttributeMaxDynamicSharedMemorySize, 100 * 1024);
    cudaFuncSetAttribute(tc_gemm_qkvg, cudaFuncAttributeMaxDynamicSharedMemorySize, GP<8>::SMEMB);
    cudaFuncSetAttribute(tc_gemm_out,  cudaFuncAttributeMaxDynamicSharedMemorySize, GP<4>::SMEMB);

    prep_kernel<<<MROWS + 5120, 256>>>(x, gamma, beta, WQ, WK, WV, Wg, WO);

    dim3 g1(DQKVG / 256, MROWS / 128);   // (16, 64)
    tc_gemm_qkvg<<<g1, 256, GP<8>::SMEMB>>>(bQ, bK, bV, bg);

    int nblk = BATCHSZ * NHEADS * NCHUNK;            // 2048
    chunk_summary<<<nblk, 256>>>(alpha);
    chunk_combine<<<BATCHSZ * NHEADS, 256>>>(alpha);
    chunk_output<<<nblk, 256, 99840>>>(alpha);

    dim3 g2(DMODEL / 128, MROWS / 128);  // (8, 64)
    tc_gemm_out<<<g2, 256, GP<4>::SMEMB>>>(bO, x, out);
}

// round 12
// speedup vs baseline: 1.0632x; 1.0632x over previous
#include <cuda_runtime.h>
#include <math.h>
#include <stdint.h>

// Problem dims
#define MROWS   8192      // B*T
#define DMODEL  1024
#define DQKVG   4096
#define NHEADS  16
#define DHEAD   64
#define TLEN    2048
#define BATCHSZ 4
#define CHUNK   64
#define NCHUNK  (TLEN / CHUNK)   // 32

// mma.sync tf32 GEMM tiling
#define KDIM    1024
#define BK      32
#define NKCH    (KDIM / BK)      // 32
#define ASTRIDE 36               // padded row stride (floats) -> conflict-free frags
#define NSTAGE  3

// Scratch (device globals — allocation-free per harness rules)
__device__ __align__(256) float g_xn[(size_t)MROWS * DMODEL];
__device__ __align__(256) float g_qkvg[(size_t)MROWS * DQKVG];
__device__ __align__(256) float g_og[(size_t)MROWS * DMODEL];
__device__ __align__(256) float g_chunkS[(size_t)BATCHSZ * NHEADS * NCHUNK * 64 * 64];
__device__ __align__(256) float g_state [(size_t)BATCHSZ * NHEADS * NCHUNK * 64 * 64];
// tf32-pre-rounded weights: [WQ;WK;WV;Wg] and WO
__device__ __align__(256) float g_wt [(size_t)DQKVG * KDIM];
__device__ __align__(256) float g_wot[(size_t)DMODEL * KDIM];

// ---------------------------------------------------------------------------
// helpers
// ---------------------------------------------------------------------------
__device__ __forceinline__ uint32_t f2tf32(float x) {
    uint32_t y;
    asm("cvt.rna.tf32.f32 %0, %1;" : "=r"(y) : "f"(x));
    return y;
}
__device__ __forceinline__ float f2tf32f(float x) {
    return __uint_as_float(f2tf32(x));
}
__device__ __forceinline__ uint32_t smem_u32(const void* p) {
    uint32_t a;
    asm("{ .reg .u64 t; cvta.to.shared.u64 t, %1; cvt.u32.u64 %0, t; }" : "=r"(a) : "l"(p));
    return a;
}
__device__ __forceinline__ void mma_tf32(float* d, const uint32_t* a, const uint32_t* b) {
    asm volatile(
        "mma.sync.aligned.m16n8k8.row.col.f32.tf32.tf32.f32 "
        "{%0,%1,%2,%3}, {%4,%5,%6,%7}, {%8,%9}, {%0,%1,%2,%3};\n"
        : "+f"(d[0]), "+f"(d[1]), "+f"(d[2]), "+f"(d[3])
        : "r"(a[0]), "r"(a[1]), "r"(a[2]), "r"(a[3]), "r"(b[0]), "r"(b[1]));
}
#define CP_ASYNC16(dst, src) \
    asm volatile("cp.async.cg.shared.global [%0], [%1], 16;\n" :: "r"(dst), "l"(src))
#define CP_COMMIT() asm volatile("cp.async.commit_group;\n" ::: "memory")
#define CP_WAIT1()  asm volatile("cp.async.wait_group 1;\n" ::: "memory")

// Geometry parametrized on NT (n-tiles of 8 per warp): BN = 32*NT
template<int NT> struct GP {
    static constexpr int BN     = NT * 32;
    static constexpr int ABUFW  = 128 * ASTRIDE;          // A words per stage
    static constexpr int BBUFW  = BN * ASTRIDE;           // B words per stage
    static constexpr int STAGEW = ABUFW + BBUFW;
    static constexpr int SMEMB  = NSTAGE * STAGEW * 4;
};

template<int NT>
__device__ __forceinline__ void issue_stage(const float* __restrict__ Ag,
                                            const float* __restrict__ Bg,
                                            uint32_t sbase, int stage, int k0,
                                            int tid) {
    uint32_t As = sbase + stage * (GP<NT>::STAGEW * 4);
    uint32_t Bs = As + GP<NT>::ABUFW * 4;
    int r0 = tid >> 3, c4 = (tid & 7) * 4;
    #pragma unroll
    for (int i = 0; i < 4; i++) {
        int r = r0 + 32 * i;
        CP_ASYNC16(As + (r * ASTRIDE + c4) * 4, Ag + (size_t)r * KDIM + k0 + c4);
    }
    #pragma unroll
    for (int i = 0; i < GP<NT>::BN / 32; i++) {
        int r = r0 + 32 * i;
        CP_ASYNC16(Bs + (r * ASTRIDE + c4) * 4, Bg + (size_t)r * KDIM + k0 + c4);
    }
}

template<int NT>
__device__ __forceinline__ void s_compute(const uint32_t* __restrict__ sm, int buf,
                                          int lane, int wm, int wn,
                                          float acc[4][NT][4]) {
    const uint32_t* As = sm + buf * GP<NT>::STAGEW;
    const uint32_t* Bs = As + GP<NT>::ABUFW;
    int mbase = wm * 64 + (lane >> 2);
    int nbase = wn * (NT * 8) + (lane >> 2);
    int kq = lane & 3;
    #pragma unroll
    for (int kk = 0; kk < 4; kk++) {
        int k0 = kk * 8 + kq;
        uint32_t a[4][4], b[NT][2];
        #pragma unroll
        for (int mt = 0; mt < 4; mt++) {
            a[mt][0] = As[(mbase + mt * 16    ) * ASTRIDE + k0];
            a[mt][1] = As[(mbase + mt * 16 + 8) * ASTRIDE + k0];
            a[mt][2] = As[(mbase + mt * 16    ) * ASTRIDE + k0 + 4];
            a[mt][3] = As[(mbase + mt * 16 + 8) * ASTRIDE + k0 + 4];
        }
        #pragma unroll
        for (int nt = 0; nt < NT; nt++) {
            b[nt][0] = Bs[(nbase + nt * 8) * ASTRIDE + k0];
            b[nt][1] = Bs[(nbase + nt * 8) * ASTRIDE + k0 + 4];
        }
        #pragma unroll
        for (int mt = 0; mt < 4; mt++)
            #pragma unroll
            for (int nt = 0; nt < NT; nt++)
                mma_tf32(acc[mt][nt], a[mt], b[nt]);
    }
}

// Mainloop, SINGLE barrier per k-chunk:
//   wait(G_c) -> sync -> compute(c) -> issue(c+2) -> commit
// Safety: the barrier at iteration c sits between compute(c-1) and compute(c)
// for every thread, so when any thread issues into slot (c+2)%3 == (c-1)%3,
// all threads have finished reading that slot. compute(c) reads slot c%3,
// disjoint from the slot being overwritten.
template<int NT>
__device__ __forceinline__ void tf32_mainloop(const float* __restrict__ Ag,
                                              const float* __restrict__ Bg,
                                              uint32_t* sm, int tid,
                                              float acc[4][NT][4]) {
    int lane = tid & 31, warp = tid >> 5;
    int wm = warp & 1, wn = warp >> 1;
    uint32_t sb = smem_u32(sm);

    issue_stage<NT>(Ag, Bg, sb, 0, 0, tid);    CP_COMMIT();
    issue_stage<NT>(Ag, Bg, sb, 1, BK, tid);   CP_COMMIT();

    #pragma unroll 1
    for (int c = 0; c < NKCH; c++) {
        CP_WAIT1();                      // group c landed (<=1 newer pending)
        __syncthreads();
        s_compute<NT>(sm, c % NSTAGE, lane, wm, wn, acc);
        if (c + 2 < NKCH)
            issue_stage<NT>(Ag, Bg, sb, (c + 2) % NSTAGE, (c + 2) * BK, tid);
        CP_COMMIT();                     // empty group on tail iters keeps numbering
    }
}

// ---------------------------------------------------------------------------
// GEMM 1: g_qkvg = g_xn @ g_wt^T + bias (+silu on G block)
// BM=128, BN=128; grid = (32, 64), 256 threads, 2 CTAs/SM
// ---------------------------------------------------------------------------
__global__ __launch_bounds__(256, 2)
void tc_gemm_qkvg(const float* __restrict__ bQ, const float* __restrict__ bK,
                  const float* __restrict__ bV, const float* __restrict__ bg) {
    extern __shared__ uint32_t sm[];
    const int NT = 4;
    int tid = threadIdx.x;
    int lane = tid & 31, warp = tid >> 5;
    int wm = warp & 1, wn = warp >> 1;
    int bn = blockIdx.x, bm = blockIdx.y;

    int cb = bn * 128;
    int which = cb >> 10;
    const float* bias;
    if      (which == 0) bias = bQ;
    else if (which == 1) bias = bK;
    else if (which == 2) bias = bV;
    else                 bias = bg;
    const float* Bg = g_wt + (size_t)cb * KDIM;
    const float* Ag = g_xn + (size_t)(bm * 128) * KDIM;

    float acc[4][NT][4];
    #pragma unroll
    for (int i = 0; i < 4; i++)
        #pragma unroll
        for (int j = 0; j < NT; j++)
            #pragma unroll
            for (int k = 0; k < 4; k++) acc[i][j][k] = 0.f;

    tf32_mainloop<NT>(Ag, Bg, sm, tid, acc);

    bool do_silu = (which == 3);
    int row0 = bm * 128 + wm * 64 + (lane >> 2);
    int col0 = cb + wn * 32 + (lane & 3) * 2;
    #pragma unroll
    for (int mt = 0; mt < 4; mt++) {
        #pragma unroll
        for (int nt = 0; nt < NT; nt++) {
            int cg = col0 + nt * 8;
            float b0 = bias[cg & 1023], b1 = bias[(cg + 1) & 1023];
            #pragma unroll
            for (int half = 0; half < 2; half++) {
                size_t row = (size_t)(row0 + mt * 16 + half * 8);
                float v0 = acc[mt][nt][half * 2 + 0] + b0;
                float v1 = acc[mt][nt][half * 2 + 1] + b1;
                if (do_silu) {
                    v0 = v0 / (1.0f + expf(-v0));
                    v1 = v1 / (1.0f + expf(-v1));
                }
                *(float2*)(g_qkvg + row * DQKVG + cg) = make_float2(v0, v1);
            }
        }
    }
}

// ---------------------------------------------------------------------------
// GEMM 2: out = g_og @ g_wot^T + bO + x   BM=128, BN=128; grid = (8, 64)
// ---------------------------------------------------------------------------
__global__ __launch_bounds__(256, 2)
void tc_gemm_out(const float* __restrict__ bO,
                 const float* __restrict__ x, float* __restrict__ out) {
    extern __shared__ uint32_t sm[];
    const int NT = 4;
    int tid = threadIdx.x;
    int lane = tid & 31, warp = tid >> 5;
    int wm = warp & 1, wn = warp >> 1;
    int bn = blockIdx.x, bm = blockIdx.y;

    int cb = bn * 128;
    const float* Bg = g_wot + (size_t)cb * KDIM;
    const float* Ag = g_og + (size_t)(bm * 128) * KDIM;

    float acc[4][NT][4];
    #pragma unroll
    for (int i = 0; i < 4; i++)
        #pragma unroll
        for (int j = 0; j < NT; j++)
            #pragma unroll
            for (int k = 0; k < 4; k++) acc[i][j][k] = 0.f;

    tf32_mainloop<NT>(Ag, Bg, sm, tid, acc);

    int row0 = bm * 128 + wm * 64 + (lane >> 2);
    int col0 = cb + wn * 32 + (lane & 3) * 2;
    #pragma unroll
    for (int mt = 0; mt < 4; mt++) {
        #pragma unroll
        for (int nt = 0; nt < NT; nt++) {
            int cg = col0 + nt * 8;
            float b0 = bO[cg], b1 = bO[cg + 1];
            #pragma unroll
            for (int half = 0; half < 2; half++) {
                size_t row = (size_t)(row0 + mt * 16 + half * 8);
                float2 xr = *(const float2*)(x + row * DMODEL + cg);
                float2 v;
                v.x = acc[mt][nt][half * 2 + 0] + b0 + xr.x;
                v.y = acc[mt][nt][half * 2 + 1] + b1 + xr.y;
                *(float2*)(out + row * DMODEL + cg) = v;
            }
        }
    }
}

// ---------------------------------------------------------------------------
// prep: fused LayerNorm (blocks 0..8191) + weight tf32 pre-round (8192..13311)
// ---------------------------------------------------------------------------
__global__ __launch_bounds__(256) void prep_kernel(
    const float* __restrict__ x,
    const float* __restrict__ gamma, const float* __restrict__ beta,
    const float* __restrict__ WQ, const float* __restrict__ WK,
    const float* __restrict__ WV, const float* __restrict__ Wg,
    const float* __restrict__ WO) {
    int blk = blockIdx.x;
    int t = threadIdx.x;
    if (blk < MROWS) {
        const float4* xr = (const float4*)(x + (size_t)blk * DMODEL);
        float4 a = xr[t];
        float s = a.x + a.y + a.z + a.w;
        float q = a.x * a.x + a.y * a.y + a.z * a.z + a.w * a.w;
        #pragma unroll
        for (int o = 16; o > 0; o >>= 1) {
            s += __shfl_xor_sync(0xffffffffu, s, o);
            q += __shfl_xor_sync(0xffffffffu, q, o);
        }
        __shared__ float ss[8], sq[8];
        int w = t >> 5, lane = t & 31;
        if (lane == 0) { ss[w] = s; sq[w] = q; }
        __syncthreads();
        float st = 0.f, qt = 0.f;
        #pragma unroll
        for (int i = 0; i < 8; i++) { st += ss[i]; qt += sq[i]; }
        float mu = st * (1.0f / DMODEL);
        float var = qt * (1.0f / DMODEL) - mu * mu;
        float rs = rsqrtf(var + 1e-5f);
        float4 gm = ((const float4*)gamma)[t];
        float4 bt = ((const float4*)beta)[t];
        float4 o;
        o.x = f2tf32f((a.x - mu) * rs * gm.x + bt.x);
        o.y = f2tf32f((a.y - mu) * rs * gm.y + bt.y);
        o.z = f2tf32f((a.z - mu) * rs * gm.z + bt.z);
        o.w = f2tf32f((a.w - mu) * rs * gm.w + bt.w);
        ((float4*)(g_xn + (size_t)blk * DMODEL))[t] = o;
    } else {
        int i = (blk - MROWS) * 256 + t;           // float4 index, < 1310720
        const float* src;
        float* dst;
        if (i < 1048576) {
            int m = i >> 18;
            int li = i & 262143;
            src = (m == 0 ? WQ : m == 1 ? WK : m == 2 ? WV : Wg) + (size_t)li * 4;
            dst = g_wt + (size_t)i * 4;
        } else {
            int li = i - 1048576;
            src = WO + (size_t)li * 4;
            dst = g_wot + (size_t)li * 4;
        }
        float4 v = *(const float4*)src;
        v.x = f2tf32f(v.x); v.y = f2tf32f(v.y);
        v.z = f2tf32f(v.z); v.w = f2tf32f(v.w);
        *(float4*)dst = v;
    }
}

// ---------------------------------------------------------------------------
// Pass 1: per-chunk state summary (unchanged)
// ---------------------------------------------------------------------------
__global__ __launch_bounds__(256) void chunk_summary(const float* __restrict__ alpha_logit) {
    int c = blockIdx.x & (NCHUNK - 1);
    int h = (blockIdx.x >> 5) & (NHEADS - 1);
    int b = blockIdx.x >> 9;

    __shared__ float Kt[64][65];
    __shared__ float Vs[64][65];
    __shared__ float lal[64];

    int tid = threadIdx.x;
    int tx = tid & 15, ty = tid >> 4;

    if (tid < 64) {
        float a = 1.0f / (1.0f + expf(-alpha_logit[h * 64 + tid]));
        lal[tid] = log2f(a);
    }
    __syncthreads();

    const float* rowb = g_qkvg + ((size_t)(b * TLEN + c * CHUNK)) * DQKVG + h * 64;
    #pragma unroll
    for (int i = 0; i < 4; i++) {
        int idx = tid + i * 256;
        int u = idx >> 4;
        int s4 = (idx & 15) << 2;
        const float* r = rowb + (size_t)u * DQKVG;
        float4 kv = *(const float4*)(r + 1024 + s4);
        float4 vv = *(const float4*)(r + 2048 + s4);
        float e = (float)(63 - u);
        Kt[u][s4 + 0] = kv.x * exp2f(lal[s4 + 0] * e);
        Kt[u][s4 + 1] = kv.y * exp2f(lal[s4 + 1] * e);
        Kt[u][s4 + 2] = kv.z * exp2f(lal[s4 + 2] * e);
        Kt[u][s4 + 3] = kv.w * exp2f(lal[s4 + 3] * e);
        Vs[u][s4 + 0] = vv.x;
        Vs[u][s4 + 1] = vv.y;
        Vs[u][s4 + 2] = vv.z;
        Vs[u][s4 + 3] = vv.w;
    }
    __syncthreads();

    float acc[4][4];
    #pragma unroll
    for (int i = 0; i < 4; i++)
        #pragma unroll
        for (int j = 0; j < 4; j++) acc[i][j] = 0.f;

    #pragma unroll 8
    for (int u = 0; u < 64; u++) {
        float ra[4], rb[4];
        #pragma unroll
        for (int i = 0; i < 4; i++) {
            ra[i] = Kt[u][ty * 4 + i];
            rb[i] = Vs[u][tx * 4 + i];
        }
        #pragma unroll
        for (int i = 0; i < 4; i++)
            #pragma unroll
            for (int j = 0; j < 4; j++)
                acc[i][j] = fmaf(ra[i], rb[j], acc[i][j]);
    }

    size_t ob = ((size_t)((b * NHEADS + h) * NCHUNK + c)) * 4096;
    #pragma unroll
    for (int i = 0; i < 4; i++)
        #pragma unroll
        for (int j = 0; j < 4; j++)
            g_chunkS[ob + (ty * 4 + i) * 64 + tx * 4 + j] = acc[i][j];
}

// ---------------------------------------------------------------------------
// Pass 2: sequential combine (unchanged)
// ---------------------------------------------------------------------------
__global__ __launch_bounds__(256) void chunk_combine(const float* __restrict__ alpha_logit) {
    int bh = blockIdx.x;
    int h = bh & (NHEADS - 1);
    int tid = threadIdx.x;

    float4 H[4];
    float aL[4];
    #pragma unroll
    for (int k = 0; k < 4; k++) {
        H[k] = make_float4(0.f, 0.f, 0.f, 0.f);
        int s = (tid + k * 256) >> 4;
        float a = 1.0f / (1.0f + expf(-alpha_logit[h * 64 + s]));
        aL[k] = exp2f(log2f(a) * 64.0f);
    }

    for (int c = 0; c < NCHUNK; c++) {
        size_t base = ((size_t)bh * NCHUNK + c) * 4096;
        #pragma unroll
        for (int k = 0; k < 4; k++) {
            int idx4 = tid + k * 256;
            ((float4*)(g_state + base))[idx4] = H[k];
            float4 S = ((const float4*)(g_chunkS + base))[idx4];
            H[k].x = aL[k] * H[k].x + S.x;
            H[k].y = aL[k] * H[k].y + S.y;
            H[k].z = aL[k] * H[k].z + S.z;
            H[k].w = aL[k] * H[k].w + S.w;
        }
    }
}

// ---------------------------------------------------------------------------
// Pass 3: intra-chunk output; epilogue writes tf32-pre-rounded g_og
// ---------------------------------------------------------------------------
__global__ __launch_bounds__(256) void chunk_output(const float* __restrict__ alpha_logit) {
    extern __shared__ float smf[];
    float (*Qt)[65] = (float(*)[65])(smf);
    float (*Ks)[65] = (float(*)[65])(smf + 4160);
    float (*Ms)[65] = (float(*)[65])(smf + 8320);
    float (*NN)[65] = (float(*)[65])(smf + 16640);

    __shared__ float al[64], lal[64];

    int c = blockIdx.x & (NCHUNK - 1);
    int h = (blockIdx.x >> 5) & (NHEADS - 1);
    int b = blockIdx.x >> 9;

    int tid = threadIdx.x;
    int tx = tid & 15, ty = tid >> 4;

    if (tid < 64) {
        float a = 1.0f / (1.0f + expf(-alpha_logit[h * 64 + tid]));
        al[tid] = a;
        lal[tid] = log2f(a);
    }
    __syncthreads();

    const float* rowb = g_qkvg + ((size_t)(b * TLEN + c * CHUNK)) * DQKVG + h * 64;
    size_t sbase = ((size_t)((b * NHEADS + h) * NCHUNK + c)) * 4096;

    #pragma unroll
    for (int i = 0; i < 4; i++) {
        int idx = tid + i * 256;
        int t = idx >> 4;
        int s4 = (idx & 15) << 2;
        const float* r = rowb + (size_t)t * DQKVG;
        float4 qv = *(const float4*)(r + s4);
        float4 kv = *(const float4*)(r + 1024 + s4);
        float4 vv = *(const float4*)(r + 2048 + s4);
        float tf = (float)t;
        Qt[s4 + 0][t] = qv.x * exp2f(lal[s4 + 0] * tf);
        Qt[s4 + 1][t] = qv.y * exp2f(lal[s4 + 1] * tf);
        Qt[s4 + 2][t] = qv.z * exp2f(lal[s4 + 2] * tf);
        Qt[s4 + 3][t] = qv.w * exp2f(lal[s4 + 3] * tf);
        Ks[s4 + 0][t] = kv.x * exp2f(-lal[s4 + 0] * tf);
        Ks[s4 + 1][t] = kv.y * exp2f(-lal[s4 + 1] * tf);
        Ks[s4 + 2][t] = kv.z * exp2f(-lal[s4 + 2] * tf);
        Ks[s4 + 3][t] = kv.w * exp2f(-lal[s4 + 3] * tf);
        NN[t][s4 + 0] = vv.x;
        NN[t][s4 + 1] = vv.y;
        NN[t][s4 + 2] = vv.z;
        NN[t][s4 + 3] = vv.w;
        float4 hv = *(const float4*)(g_state + sbase + (size_t)idx * 4);
        NN[64 + t][s4 + 0] = hv.x;
        NN[64 + t][s4 + 1] = hv.y;
        NN[64 + t][s4 + 2] = hv.z;
        NN[64 + t][s4 + 3] = hv.w;
    }
    __syncthreads();

    float acc[4][4];
    #pragma unroll
    for (int i = 0; i < 4; i++)
        #pragma unroll
        for (int j = 0; j < 4; j++) acc[i][j] = 0.f;

    #pragma unroll 8
    for (int s = 0; s < 64; s++) {
        float ra[4], rb[4];
        #pragma unroll
        for (int i = 0; i < 4; i++) {
            ra[i] = Qt[s][ty * 4 + i];
            rb[i] = Ks[s][tx * 4 + i];
        }
        #pragma unroll
        for (int i = 0; i < 4; i++)
            #pragma unroll
            for (int j = 0; j < 4; j++)
                acc[i][j] = fmaf(ra[i], rb[j], acc[i][j]);
    }

    #pragma unroll
    for (int i = 0; i < 4; i++) {
        int t = ty * 4 + i;
        #pragma unroll
        for (int j = 0; j < 4; j++) {
            int u = tx * 4 + j;
            Ms[u][t] = (u <= t) ? acc[i][j] : 0.f;
        }
    }
    #pragma unroll
    for (int i = 0; i < 4; i++) {
        int idx = tid + i * 256;
        int s = idx >> 4;
        int t4 = (idx & 15) << 2;
        float a = al[s];
        #pragma unroll
        for (int j = 0; j < 4; j++)
            Ms[64 + s][t4 + j] = Qt[s][t4 + j] * a;
    }
    __syncthreads();

    float o[4][4];
    #pragma unroll
    for (int i = 0; i < 4; i++)
        #pragma unroll
        for (int j = 0; j < 4; j++) o[i][j] = 0.f;

    #pragma unroll 8
    for (int jj = 0; jj < 128; jj++) {
        float ra[4], rb[4];
        #pragma unroll
        for (int i = 0; i < 4; i++) {
            ra[i] = Ms[jj][ty * 4 + i];
            rb[i] = NN[jj][tx * 4 + i];
        }
        #pragma unroll
        for (int i = 0; i < 4; i++)
            #pragma unroll
            for (int j = 0; j < 4; j++)
                o[i][j] = fmaf(ra[i], rb[j], o[i][j]);
    }

    float* ogb = g_og + ((size_t)(b * TLEN + c * CHUNK)) * DMODEL + h * 64;
    #pragma unroll
    for (int i = 0; i < 4; i++) {
        int t = ty * 4 + i;
        const float* gr = rowb + (size_t)t * DQKVG + 3072 + tx * 4;
        float4 g = *(const float4*)gr;
        float4 ov;
        ov.x = f2tf32f(o[i][0] * g.x);
        ov.y = f2tf32f(o[i][1] * g.y);
        ov.z = f2tf32f(o[i][2] * g.z);
        ov.w = f2tf32f(o[i][3] * g.w);
        *(float4*)(ogb + (size_t)t * DMODEL + tx * 4) = ov;
    }
}

// ---------------------------------------------------------------------------
extern "C" void kernel_launch(void* const* d_in, const int* in_sizes, int n_in,
                              void* d_out, int out_size) {
    const float* x      = (const float*)d_in[0];
    const float* WQ     = (const float*)d_in[1];
    const float* bQ     = (const float*)d_in[2];
    const float* WK     = (const float*)d_in[3];
    const float* bK     = (const float*)d_in[4];
    const float* WV     = (const float*)d_in[5];
    const float* bV     = (const float*)d_in[6];
    const float* WO     = (const float*)d_in[7];
    const float* bO     = (const float*)d_in[8];
    const float* Wg     = (const float*)d_in[9];
    const float* bg     = (const float*)d_in[10];
    const float* alpha  = (const float*)d_in[11];
    const float* gamma  = (const float*)d_in[12];
    const float* beta   = (const float*)d_in[13];
    float* out = (float*)d_out;

    cudaFuncSetAttribute(chunk_output, cudaFuncAttributeMaxDynamicSharedMemorySize, 100 * 1024);
    cudaFuncSetAttribute(tc_gemm_qkvg, cudaFuncAttributeMaxDynamicSharedMemorySize, GP<4>::SMEMB);
    cudaFuncSetAttribute(tc_gemm_out,  cudaFuncAttributeMaxDynamicSharedMemorySize, GP<4>::SMEMB);

    prep_kernel<<<MROWS + 5120, 256>>>(x, gamma, beta, WQ, WK, WV, Wg, WO);

    dim3 g1(DQKVG / 128, MROWS / 128);   // (32, 64)
    tc_gemm_qkvg<<<g1, 256, GP<4>::SMEMB>>>(bQ, bK, bV, bg);

    int nblk = BATCHSZ * NHEADS * NCHUNK;            // 2048
    chunk_summary<<<nblk, 256>>>(alpha);
    chunk_combine<<<BATCHSZ * NHEADS, 256>>>(alpha);
    chunk_output<<<nblk, 256, 99840>>>(alpha);

    dim3 g2(DMODEL / 128, MROWS / 128);  // (8, 64)
    tc_gemm_out<<<g2, 256, GP<4>::SMEMB>>>(bO, x, out);
}

// round 13
// speedup vs baseline: 1.1728x; 1.1031x over previous
#include <cuda_runtime.h>
#include <math.h>
#include <stdint.h>

// Problem dims
#define MROWS   8192      // B*T
#define DMODEL  1024
#define DQKVG   4096
#define NHEADS  16
#define DHEAD   64
#define TLEN    2048
#define BATCHSZ 4
#define CHUNK   64
#define NCHUNK  (TLEN / CHUNK)   // 32

// mma.sync tf32 GEMM tiling
#define KDIM    1024
#define BK      32
#define NKCH    (KDIM / BK)      // 32
#define ASTRIDE 36               // padded row stride (floats) -> conflict-free frags
#define NSTAGE  3

// Scratch (device globals — allocation-free per harness rules)
__device__ __align__(256) float g_xn[(size_t)MROWS * DMODEL];
__device__ __align__(256) float g_qkvg[(size_t)MROWS * DQKVG];
__device__ __align__(256) float g_og[(size_t)MROWS * DMODEL];
__device__ __align__(256) float g_chunkS[(size_t)BATCHSZ * NHEADS * NCHUNK * 64 * 64];
__device__ __align__(256) float g_state [(size_t)BATCHSZ * NHEADS * NCHUNK * 64 * 64];
// tf32-pre-rounded weights: [WQ;WK;WV;Wg] and WO
__device__ __align__(256) float g_wt [(size_t)DQKVG * KDIM];
__device__ __align__(256) float g_wot[(size_t)DMODEL * KDIM];

// ---------------------------------------------------------------------------
// helpers
// ---------------------------------------------------------------------------
__device__ __forceinline__ uint32_t f2tf32(float x) {
    uint32_t y;
    asm("cvt.rna.tf32.f32 %0, %1;" : "=r"(y) : "f"(x));
    return y;
}
__device__ __forceinline__ float f2tf32f(float x) {
    return __uint_as_float(f2tf32(x));
}
__device__ __forceinline__ uint32_t smem_u32(const void* p) {
    uint32_t a;
    asm("{ .reg .u64 t; cvta.to.shared.u64 t, %1; cvt.u32.u64 %0, t; }" : "=r"(a) : "l"(p));
    return a;
}
__device__ __forceinline__ void mma_tf32(float* d, const uint32_t* a, const uint32_t* b) {
    asm volatile(
        "mma.sync.aligned.m16n8k8.row.col.f32.tf32.tf32.f32 "
        "{%0,%1,%2,%3}, {%4,%5,%6,%7}, {%8,%9}, {%0,%1,%2,%3};\n"
        : "+f"(d[0]), "+f"(d[1]), "+f"(d[2]), "+f"(d[3])
        : "r"(a[0]), "r"(a[1]), "r"(a[2]), "r"(a[3]), "r"(b[0]), "r"(b[1]));
}
#define CP_ASYNC16(dst, src) \
    asm volatile("cp.async.cg.shared.global [%0], [%1], 16;\n" :: "r"(dst), "l"(src))
#define CP_COMMIT() asm volatile("cp.async.commit_group;\n" ::: "memory")
#define CP_WAIT1()  asm volatile("cp.async.wait_group 1;\n" ::: "memory")

// Geometry parametrized on NT (n-tiles of 8 per warp): BN = 32*NT
template<int NT> struct GP {
    static constexpr int BN     = NT * 32;
    static constexpr int ABUFW  = 128 * ASTRIDE;
    static constexpr int BBUFW  = BN * ASTRIDE;
    static constexpr int STAGEW = ABUFW + BBUFW;
    static constexpr int SMEMB  = NSTAGE * STAGEW * 4;
};

template<int NT>
__device__ __forceinline__ void issue_stage(const float* __restrict__ Ag,
                                            const float* __restrict__ Bg,
                                            uint32_t sbase, int stage, int k0,
                                            int tid) {
    uint32_t As = sbase + stage * (GP<NT>::STAGEW * 4);
    uint32_t Bs = As + GP<NT>::ABUFW * 4;
    int r0 = tid >> 3, c4 = (tid & 7) * 4;
    #pragma unroll
    for (int i = 0; i < 4; i++) {
        int r = r0 + 32 * i;
        CP_ASYNC16(As + (r * ASTRIDE + c4) * 4, Ag + (size_t)r * KDIM + k0 + c4);
    }
    #pragma unroll
    for (int i = 0; i < GP<NT>::BN / 32; i++) {
        int r = r0 + 32 * i;
        CP_ASYNC16(Bs + (r * ASTRIDE + c4) * 4, Bg + (size_t)r * KDIM + k0 + c4);
    }
}

template<int NT>
__device__ __forceinline__ void s_compute(const uint32_t* __restrict__ sm, int buf,
                                          int lane, int wm, int wn,
                                          float acc[4][NT][4]) {
    const uint32_t* As = sm + buf * GP<NT>::STAGEW;
    const uint32_t* Bs = As + GP<NT>::ABUFW;
    int mbase = wm * 64 + (lane >> 2);
    int nbase = wn * (NT * 8) + (lane >> 2);
    int kq = lane & 3;
    #pragma unroll
    for (int kk = 0; kk < 4; kk++) {
        int k0 = kk * 8 + kq;
        uint32_t a[4][4], b[NT][2];
        #pragma unroll
        for (int mt = 0; mt < 4; mt++) {
            a[mt][0] = As[(mbase + mt * 16    ) * ASTRIDE + k0];
            a[mt][1] = As[(mbase + mt * 16 + 8) * ASTRIDE + k0];
            a[mt][2] = As[(mbase + mt * 16    ) * ASTRIDE + k0 + 4];
            a[mt][3] = As[(mbase + mt * 16 + 8) * ASTRIDE + k0 + 4];
        }
        #pragma unroll
        for (int nt = 0; nt < NT; nt++) {
            b[nt][0] = Bs[(nbase + nt * 8) * ASTRIDE + k0];
            b[nt][1] = Bs[(nbase + nt * 8) * ASTRIDE + k0 + 4];
        }
        #pragma unroll
        for (int mt = 0; mt < 4; mt++)
            #pragma unroll
            for (int nt = 0; nt < NT; nt++)
                mma_tf32(acc[mt][nt], a[mt], b[nt]);
    }
}

// Mainloop, single barrier per k-chunk (see R12 analysis)
template<int NT>
__device__ __forceinline__ void tf32_mainloop(const float* __restrict__ Ag,
                                              const float* __restrict__ Bg,
                                              uint32_t* sm, int tid,
                                              float acc[4][NT][4]) {
    int lane = tid & 31, warp = tid >> 5;
    int wm = warp & 1, wn = warp >> 1;
    uint32_t sb = smem_u32(sm);

    issue_stage<NT>(Ag, Bg, sb, 0, 0, tid);    CP_COMMIT();
    issue_stage<NT>(Ag, Bg, sb, 1, BK, tid);   CP_COMMIT();

    #pragma unroll 1
    for (int c = 0; c < NKCH; c++) {
        CP_WAIT1();
        __syncthreads();
        s_compute<NT>(sm, c % NSTAGE, lane, wm, wn, acc);
        if (c + 2 < NKCH)
            issue_stage<NT>(Ag, Bg, sb, (c + 2) % NSTAGE, (c + 2) * BK, tid);
        CP_COMMIT();
    }
}

// ---------------------------------------------------------------------------
// GEMM 1: g_qkvg = g_xn @ g_wt^T + bias (+silu on G block)
// ---------------------------------------------------------------------------
__global__ __launch_bounds__(256, 2)
void tc_gemm_qkvg(const float* __restrict__ bQ, const float* __restrict__ bK,
                  const float* __restrict__ bV, const float* __restrict__ bg) {
    extern __shared__ uint32_t sm[];
    const int NT = 4;
    int tid = threadIdx.x;
    int lane = tid & 31, warp = tid >> 5;
    int wm = warp & 1, wn = warp >> 1;
    int bn = blockIdx.x, bm = blockIdx.y;

    int cb = bn * 128;
    int which = cb >> 10;
    const float* bias;
    if      (which == 0) bias = bQ;
    else if (which == 1) bias = bK;
    else if (which == 2) bias = bV;
    else                 bias = bg;
    const float* Bg = g_wt + (size_t)cb * KDIM;
    const float* Ag = g_xn + (size_t)(bm * 128) * KDIM;

    float acc[4][NT][4];
    #pragma unroll
    for (int i = 0; i < 4; i++)
        #pragma unroll
        for (int j = 0; j < NT; j++)
            #pragma unroll
            for (int k = 0; k < 4; k++) acc[i][j][k] = 0.f;

    tf32_mainloop<NT>(Ag, Bg, sm, tid, acc);

    bool do_silu = (which == 3);
    int row0 = bm * 128 + wm * 64 + (lane >> 2);
    int col0 = cb + wn * 32 + (lane & 3) * 2;
    #pragma unroll
    for (int mt = 0; mt < 4; mt++) {
        #pragma unroll
        for (int nt = 0; nt < NT; nt++) {
            int cg = col0 + nt * 8;
            float b0 = bias[cg & 1023], b1 = bias[(cg + 1) & 1023];
            #pragma unroll
            for (int half = 0; half < 2; half++) {
                size_t row = (size_t)(row0 + mt * 16 + half * 8);
                float v0 = acc[mt][nt][half * 2 + 0] + b0;
                float v1 = acc[mt][nt][half * 2 + 1] + b1;
                if (do_silu) {
                    v0 = v0 / (1.0f + expf(-v0));
                    v1 = v1 / (1.0f + expf(-v1));
                }
                *(float2*)(g_qkvg + row * DQKVG + cg) = make_float2(v0, v1);
            }
        }
    }
}

// ---------------------------------------------------------------------------
// GEMM 2: out = g_og @ g_wot^T + bO + x
// ---------------------------------------------------------------------------
__global__ __launch_bounds__(256, 2)
void tc_gemm_out(const float* __restrict__ bO,
                 const float* __restrict__ x, float* __restrict__ out) {
    extern __shared__ uint32_t sm[];
    const int NT = 4;
    int tid = threadIdx.x;
    int lane = tid & 31, warp = tid >> 5;
    int wm = warp & 1, wn = warp >> 1;
    int bn = blockIdx.x, bm = blockIdx.y;

    int cb = bn * 128;
    const float* Bg = g_wot + (size_t)cb * KDIM;
    const float* Ag = g_og + (size_t)(bm * 128) * KDIM;

    float acc[4][NT][4];
    #pragma unroll
    for (int i = 0; i < 4; i++)
        #pragma unroll
        for (int j = 0; j < NT; j++)
            #pragma unroll
            for (int k = 0; k < 4; k++) acc[i][j][k] = 0.f;

    tf32_mainloop<NT>(Ag, Bg, sm, tid, acc);

    int row0 = bm * 128 + wm * 64 + (lane >> 2);
    int col0 = cb + wn * 32 + (lane & 3) * 2;
    #pragma unroll
    for (int mt = 0; mt < 4; mt++) {
        #pragma unroll
        for (int nt = 0; nt < NT; nt++) {
            int cg = col0 + nt * 8;
            float b0 = bO[cg], b1 = bO[cg + 1];
            #pragma unroll
            for (int half = 0; half < 2; half++) {
                size_t row = (size_t)(row0 + mt * 16 + half * 8);
                float2 xr = *(const float2*)(x + row * DMODEL + cg);
                float2 v;
                v.x = acc[mt][nt][half * 2 + 0] + b0 + xr.x;
                v.y = acc[mt][nt][half * 2 + 1] + b1 + xr.y;
                *(float2*)(out + row * DMODEL + cg) = v;
            }
        }
    }
}

// ---------------------------------------------------------------------------
// prep: fused LayerNorm + weight tf32 pre-round (unchanged)
// ---------------------------------------------------------------------------
__global__ __launch_bounds__(256) void prep_kernel(
    const float* __restrict__ x,
    const float* __restrict__ gamma, const float* __restrict__ beta,
    const float* __restrict__ WQ, const float* __restrict__ WK,
    const float* __restrict__ WV, const float* __restrict__ Wg,
    const float* __restrict__ WO) {
    int blk = blockIdx.x;
    int t = threadIdx.x;
    if (blk < MROWS) {
        const float4* xr = (const float4*)(x + (size_t)blk * DMODEL);
        float4 a = xr[t];
        float s = a.x + a.y + a.z + a.w;
        float q = a.x * a.x + a.y * a.y + a.z * a.z + a.w * a.w;
        #pragma unroll
        for (int o = 16; o > 0; o >>= 1) {
            s += __shfl_xor_sync(0xffffffffu, s, o);
            q += __shfl_xor_sync(0xffffffffu, q, o);
        }
        __shared__ float ss[8], sq[8];
        int w = t >> 5, lane = t & 31;
        if (lane == 0) { ss[w] = s; sq[w] = q; }
        __syncthreads();
        float st = 0.f, qt = 0.f;
        #pragma unroll
        for (int i = 0; i < 8; i++) { st += ss[i]; qt += sq[i]; }
        float mu = st * (1.0f / DMODEL);
        float var = qt * (1.0f / DMODEL) - mu * mu;
        float rs = rsqrtf(var + 1e-5f);
        float4 gm = ((const float4*)gamma)[t];
        float4 bt = ((const float4*)beta)[t];
        float4 o;
        o.x = f2tf32f((a.x - mu) * rs * gm.x + bt.x);
        o.y = f2tf32f((a.y - mu) * rs * gm.y + bt.y);
        o.z = f2tf32f((a.z - mu) * rs * gm.z + bt.z);
        o.w = f2tf32f((a.w - mu) * rs * gm.w + bt.w);
        ((float4*)(g_xn + (size_t)blk * DMODEL))[t] = o;
    } else {
        int i = (blk - MROWS) * 256 + t;
        const float* src;
        float* dst;
        if (i < 1048576) {
            int m = i >> 18;
            int li = i & 262143;
            src = (m == 0 ? WQ : m == 1 ? WK : m == 2 ? WV : Wg) + (size_t)li * 4;
            dst = g_wt + (size_t)i * 4;
        } else {
            int li = i - 1048576;
            src = WO + (size_t)li * 4;
            dst = g_wot + (size_t)li * 4;
        }
        float4 v = *(const float4*)src;
        v.x = f2tf32f(v.x); v.y = f2tf32f(v.y);
        v.z = f2tf32f(v.z); v.w = f2tf32f(v.w);
        *(float4*)dst = v;
    }
}

// ---------------------------------------------------------------------------
// Pass 1: chunk_summary via mma.sync tf32
// S[s][d] = sum_u (k_u[s]*a_s^(63-u)) * v_u[d]
// A (row-major): Kts[s][u] stride 68;  B (n-major): Vt[d][u] stride 68
// ---------------------------------------------------------------------------
__global__ __launch_bounds__(256) void chunk_summary(const float* __restrict__ alpha_logit) {
    __shared__ float Kts[64 * 68];
    __shared__ float Vt [64 * 68];
    __shared__ float lal[64];

    int c = blockIdx.x & (NCHUNK - 1);
    int h = (blockIdx.x >> 5) & (NHEADS - 1);
    int b = blockIdx.x >> 9;

    int tid = threadIdx.x;
    int lane = tid & 31, wid = tid >> 5;
    int g4 = lane >> 2, q4 = lane & 3;

    if (tid < 64) {
        float a = 1.0f / (1.0f + expf(-alpha_logit[h * 64 + tid]));
        lal[tid] = log2f(a);
    }
    __syncthreads();

    const float* rowb = g_qkvg + ((size_t)(b * TLEN + c * CHUNK)) * DQKVG + h * 64;
    #pragma unroll
    for (int i = 0; i < 4; i++) {
        int idx = tid + i * 256;
        int u = idx >> 4;
        int s4 = (idx & 15) << 2;
        const float* r = rowb + (size_t)u * DQKVG;
        float4 kv = *(const float4*)(r + 1024 + s4);
        float4 vv = *(const float4*)(r + 2048 + s4);
        float e = (float)(63 - u);
        Kts[(s4 + 0) * 68 + u] = kv.x * exp2f(lal[s4 + 0] * e);
        Kts[(s4 + 1) * 68 + u] = kv.y * exp2f(lal[s4 + 1] * e);
        Kts[(s4 + 2) * 68 + u] = kv.z * exp2f(lal[s4 + 2] * e);
        Kts[(s4 + 3) * 68 + u] = kv.w * exp2f(lal[s4 + 3] * e);
        Vt[(s4 + 0) * 68 + u] = vv.x;
        Vt[(s4 + 1) * 68 + u] = vv.y;
        Vt[(s4 + 2) * 68 + u] = vv.z;
        Vt[(s4 + 3) * 68 + u] = vv.w;
    }
    __syncthreads();

    // M=64 (s), N=64 (d), K=64 (u); warps 2M x 4N
    int wm = wid & 1, wn = wid >> 1;
    int moff = wm * 32, noff = wn * 16;
    const uint32_t* Ka = (const uint32_t*)Kts;
    const uint32_t* Vb = (const uint32_t*)Vt;

    float acc[2][2][4];
    #pragma unroll
    for (int i = 0; i < 2; i++)
        #pragma unroll
        for (int j = 0; j < 2; j++)
            #pragma unroll
            for (int k = 0; k < 4; k++) acc[i][j][k] = 0.f;

    #pragma unroll
    for (int kk = 0; kk < 8; kk++) {
        int k0 = kk * 8 + q4;
        uint32_t a[2][4], bf[2][2];
        #pragma unroll
        for (int mt = 0; mt < 2; mt++) {
            int row = moff + mt * 16 + g4;
            a[mt][0] = Ka[row * 68 + k0];
            a[mt][1] = Ka[(row + 8) * 68 + k0];
            a[mt][2] = Ka[row * 68 + k0 + 4];
            a[mt][3] = Ka[(row + 8) * 68 + k0 + 4];
        }
        #pragma unroll
        for (int nt = 0; nt < 2; nt++) {
            int nr = noff + nt * 8 + g4;
            bf[nt][0] = Vb[nr * 68 + k0];
            bf[nt][1] = Vb[nr * 68 + k0 + 4];
        }
        #pragma unroll
        for (int mt = 0; mt < 2; mt++)
            #pragma unroll
            for (int nt = 0; nt < 2; nt++)
                mma_tf32(acc[mt][nt], a[mt], bf[nt]);
    }

    size_t ob = ((size_t)((b * NHEADS + h) * NCHUNK + c)) * 4096;
    #pragma unroll
    for (int mt = 0; mt < 2; mt++)
        #pragma unroll
        for (int nt = 0; nt < 2; nt++)
            #pragma unroll
            for (int half = 0; half < 2; half++) {
                int s = moff + mt * 16 + g4 + half * 8;
                int d = noff + nt * 8 + q4 * 2;
                *(float2*)(g_chunkS + ob + s * 64 + d) =
                    make_float2(acc[mt][nt][half * 2], acc[mt][nt][half * 2 + 1]);
            }
}

// ---------------------------------------------------------------------------
// Pass 2: sequential combine (unchanged)
// ---------------------------------------------------------------------------
__global__ __launch_bounds__(256) void chunk_combine(const float* __restrict__ alpha_logit) {
    int bh = blockIdx.x;
    int h = bh & (NHEADS - 1);
    int tid = threadIdx.x;

    float4 H[4];
    float aL[4];
    #pragma unroll
    for (int k = 0; k < 4; k++) {
        H[k] = make_float4(0.f, 0.f, 0.f, 0.f);
        int s = (tid + k * 256) >> 4;
        float a = 1.0f / (1.0f + expf(-alpha_logit[h * 64 + s]));
        aL[k] = exp2f(log2f(a) * 64.0f);
    }

    for (int c = 0; c < NCHUNK; c++) {
        size_t base = ((size_t)bh * NCHUNK + c) * 4096;
        #pragma unroll
        for (int k = 0; k < 4; k++) {
            int idx4 = tid + k * 256;
            ((float4*)(g_state + base))[idx4] = H[k];
            float4 S = ((const float4*)(g_chunkS + base))[idx4];
            H[k].x = aL[k] * H[k].x + S.x;
            H[k].y = aL[k] * H[k].y + S.y;
            H[k].z = aL[k] * H[k].z + S.z;
            H[k].w = aL[k] * H[k].w + S.w;
        }
    }
}

// ---------------------------------------------------------------------------
// Pass 3: chunk_output via mma.sync tf32
//   GEMM1: scores[t][u] = sum_s Qtt[t][s]*Kst[u][s]   (then causal mask)
//   GEMM2: o[t][d] = sum_j Msr[t][j]*NNt[d][j], j in [0,128)
// smem: Qtt[64][68] (A1, row-major), Kst[64][68] (B1, n-major),
//       Msr[64][132] (A2: scores | q2), NNt[64][132] (B2: V | H, n-major)
// ---------------------------------------------------------------------------
__global__ __launch_bounds__(256) void chunk_output(const float* __restrict__ alpha_logit) {
    extern __shared__ float smf[];
    float* Qtt = smf;            // [t][s] stride 68
    float* Kst = smf + 4352;     // [u][s] stride 68
    float* Msr = smf + 8704;     // [t][j] stride 132
    float* NNt = smf + 17152;    // [d][j] stride 132

    __shared__ float al[64], lal[64];

    int c = blockIdx.x & (NCHUNK - 1);
    int h = (blockIdx.x >> 5) & (NHEADS - 1);
    int b = blockIdx.x >> 9;

    int tid = threadIdx.x;
    int lane = tid & 31, wid = tid >> 5;
    int g4 = lane >> 2, q4 = lane & 3;

    if (tid < 64) {
        float a = 1.0f / (1.0f + expf(-alpha_logit[h * 64 + tid]));
        al[tid] = a;
        lal[tid] = log2f(a);
    }
    __syncthreads();

    const float* rowb = g_qkvg + ((size_t)(b * TLEN + c * CHUNK)) * DQKVG + h * 64;
    size_t sbase = ((size_t)((b * NHEADS + h) * NCHUNK + c)) * 4096;

    #pragma unroll
    for (int i = 0; i < 4; i++) {
        int idx = tid + i * 256;
        int t = idx >> 4;
        int s4 = (idx & 15) << 2;
        const float* r = rowb + (size_t)t * DQKVG;
        float4 qv = *(const float4*)(r + s4);
        float4 kv = *(const float4*)(r + 1024 + s4);
        float4 vv = *(const float4*)(r + 2048 + s4);
        float tf = (float)t;
        float4 qs;
        qs.x = qv.x * exp2f(lal[s4 + 0] * tf);
        qs.y = qv.y * exp2f(lal[s4 + 1] * tf);
        qs.z = qv.z * exp2f(lal[s4 + 2] * tf);
        qs.w = qv.w * exp2f(lal[s4 + 3] * tf);
        *(float4*)&Qtt[t * 68 + s4] = qs;
        float4 ks;
        ks.x = kv.x * exp2f(-lal[s4 + 0] * tf);
        ks.y = kv.y * exp2f(-lal[s4 + 1] * tf);
        ks.z = kv.z * exp2f(-lal[s4 + 2] * tf);
        ks.w = kv.w * exp2f(-lal[s4 + 3] * tf);
        *(float4*)&Kst[t * 68 + s4] = ks;
        // V rows -> NNt[d][t]
        NNt[(s4 + 0) * 132 + t] = vv.x;
        NNt[(s4 + 1) * 132 + t] = vv.y;
        NNt[(s4 + 2) * 132 + t] = vv.z;
        NNt[(s4 + 3) * 132 + t] = vv.w;
        // H rows (g_state is [s][d]; here row index = s = t-slot, cols s4..)
        float4 hv = *(const float4*)(g_state + sbase + (size_t)idx * 4);
        NNt[(s4 + 0) * 132 + 64 + t] = hv.x;
        NNt[(s4 + 1) * 132 + 64 + t] = hv.y;
        NNt[(s4 + 2) * 132 + 64 + t] = hv.z;
        NNt[(s4 + 3) * 132 + 64 + t] = hv.w;
    }
    __syncthreads();

    // GEMM1: M=64 (t), N=64 (u), K=64 (s); warps 2M x 4N
    int wm = wid & 1, wn = wid >> 1;
    int moff = wm * 32, noff = wn * 16;
    const uint32_t* Qa = (const uint32_t*)Qtt;
    const uint32_t* Kb = (const uint32_t*)Kst;

    float sc[2][2][4];
    #pragma unroll
    for (int i = 0; i < 2; i++)
        #pragma unroll
        for (int j = 0; j < 2; j++)
            #pragma unroll
            for (int k = 0; k < 4; k++) sc[i][j][k] = 0.f;

    #pragma unroll
    for (int kk = 0; kk < 8; kk++) {
        int k0 = kk * 8 + q4;
        uint32_t a[2][4], bf[2][2];
        #pragma unroll
        for (int mt = 0; mt < 2; mt++) {
            int row = moff + mt * 16 + g4;
            a[mt][0] = Qa[row * 68 + k0];
            a[mt][1] = Qa[(row + 8) * 68 + k0];
            a[mt][2] = Qa[row * 68 + k0 + 4];
            a[mt][3] = Qa[(row + 8) * 68 + k0 + 4];
        }
        #pragma unroll
        for (int nt = 0; nt < 2; nt++) {
            int nr = noff + nt * 8 + g4;
            bf[nt][0] = Kb[nr * 68 + k0];
            bf[nt][1] = Kb[nr * 68 + k0 + 4];
        }
        #pragma unroll
        for (int mt = 0; mt < 2; mt++)
            #pragma unroll
            for (int nt = 0; nt < 2; nt++)
                mma_tf32(sc[mt][nt], a[mt], bf[nt]);
    }

    // masked scores -> Msr[t][u]
    #pragma unroll
    for (int mt = 0; mt < 2; mt++)
        #pragma unroll
        for (int nt = 0; nt < 2; nt++)
            #pragma unroll
            for (int e = 0; e < 4; e++) {
                int t = moff + mt * 16 + g4 + (e >> 1) * 8;
                int u = noff + nt * 8 + q4 * 2 + (e & 1);
                Msr[t * 132 + u] = (u <= t) ? sc[mt][nt][e] : 0.f;
            }
    // q2 part: Msr[t][64+s] = Qtt[t][s] * al[s]
    #pragma unroll
    for (int i = 0; i < 16; i++) {
        int e = tid + i * 256;       // 0..4095
        int t = e >> 6;
        int s = e & 63;
        Msr[t * 132 + 64 + s] = Qtt[t * 68 + s] * al[s];
    }
    __syncthreads();

    // GEMM2: M=64 (t), N=64 (d), K=128 (j)
    const uint32_t* Ma = (const uint32_t*)Msr;
    const uint32_t* Nb = (const uint32_t*)NNt;

    float oc[2][2][4];
    #pragma unroll
    for (int i = 0; i < 2; i++)
        #pragma unroll
        for (int j = 0; j < 2; j++)
            #pragma unroll
            for (int k = 0; k < 4; k++) oc[i][j][k] = 0.f;

    #pragma unroll
    for (int kk = 0; kk < 16; kk++) {
        int k0 = kk * 8 + q4;
        uint32_t a[2][4], bf[2][2];
        #pragma unroll
        for (int mt = 0; mt < 2; mt++) {
            int row = moff + mt * 16 + g4;
            a[mt][0] = Ma[row * 132 + k0];
            a[mt][1] = Ma[(row + 8) * 132 + k0];
            a[mt][2] = Ma[row * 132 + k0 + 4];
            a[mt][3] = Ma[(row + 8) * 132 + k0 + 4];
        }
        #pragma unroll
        for (int nt = 0; nt < 2; nt++) {
            int nr = noff + nt * 8 + g4;
            bf[nt][0] = Nb[nr * 132 + k0];
            bf[nt][1] = Nb[nr * 132 + k0 + 4];
        }
        #pragma unroll
        for (int mt = 0; mt < 2; mt++)
            #pragma unroll
            for (int nt = 0; nt < 2; nt++)
                mma_tf32(oc[mt][nt], a[mt], bf[nt]);
    }

    // epilogue: o * silu_gate -> g_og (tf32-pre-rounded)
    float* ogb = g_og + ((size_t)(b * TLEN + c * CHUNK)) * DMODEL + h * 64;
    #pragma unroll
    for (int mt = 0; mt < 2; mt++)
        #pragma unroll
        for (int nt = 0; nt < 2; nt++)
            #pragma unroll
            for (int half = 0; half < 2; half++) {
                int t = moff + mt * 16 + g4 + half * 8;
                int d = noff + nt * 8 + q4 * 2;
                float2 g = *(const float2*)(rowb + (size_t)t * DQKVG + 3072 + d);
                float2 ov;
                ov.x = f2tf32f(oc[mt][nt][half * 2 + 0] * g.x);
                ov.y = f2tf32f(oc[mt][nt][half * 2 + 1] * g.y);
                *(float2*)(ogb + (size_t)t * DMODEL + d) = ov;
            }
}

#define CO_SMEM (25600 * 4)   // Qtt+Kst+Msr+NNt = 102400 bytes

// ---------------------------------------------------------------------------
extern "C" void kernel_launch(void* const* d_in, const int* in_sizes, int n_in,
                              void* d_out, int out_size) {
    const float* x      = (const float*)d_in[0];
    const float* WQ     = (const float*)d_in[1];
    const float* bQ     = (const float*)d_in[2];
    const float* WK     = (const float*)d_in[3];
    const float* bK     = (const float*)d_in[4];
    const float* WV     = (const float*)d_in[5];
    const float* bV     = (const float*)d_in[6];
    const float* WO     = (const float*)d_in[7];
    const float* bO     = (const float*)d_in[8];
    const float* Wg     = (const float*)d_in[9];
    const float* bg     = (const float*)d_in[10];
    const float* alpha  = (const float*)d_in[11];
    const float* gamma  = (const float*)d_in[12];
    const float* beta   = (const float*)d_in[13];
    float* out = (float*)d_out;

    cudaFuncSetAttribute(chunk_output, cudaFuncAttributeMaxDynamicSharedMemorySize, CO_SMEM);
    cudaFuncSetAttribute(tc_gemm_qkvg, cudaFuncAttributeMaxDynamicSharedMemorySize, GP<4>::SMEMB);
    cudaFuncSetAttribute(tc_gemm_out,  cudaFuncAttributeMaxDynamicSharedMemorySize, GP<4>::SMEMB);

    prep_kernel<<<MROWS + 5120, 256>>>(x, gamma, beta, WQ, WK, WV, Wg, WO);

    dim3 g1(DQKVG / 128, MROWS / 128);   // (32, 64)
    tc_gemm_qkvg<<<g1, 256, GP<4>::SMEMB>>>(bQ, bK, bV, bg);

    int nblk = BATCHSZ * NHEADS * NCHUNK;            // 2048
    chunk_summary<<<nblk, 256>>>(alpha);
    chunk_combine<<<BATCHSZ * NHEADS, 256>>>(alpha);
    chunk_output<<<nblk, 256, CO_SMEM>>>(alpha);

    dim3 g2(DMODEL / 128, MROWS / 128);  // (8, 64)
    tc_gemm_out<<<g2, 256, GP<4>::SMEMB>>>(bO, x, out);
}

// round 16
// speedup vs baseline: 1.2553x; 1.0703x over previous
#include <cuda_runtime.h>
#include <math.h>
#include <stdint.h>

// Problem dims
#define MROWS   8192      // B*T
#define DMODEL  1024
#define DQKVG   4096
#define NHEADS  16
#define DHEAD   64
#define TLEN    2048
#define BATCHSZ 4
#define CHUNK   64
#define NCHUNK  (TLEN / CHUNK)   // 32

// mma.sync tf32 GEMM tiling
#define KDIM    1024
#define BK      32
#define NKCH    (KDIM / BK)      // 32
#define ASTRIDE 36               // padded row stride (floats)
#define NSTAGE  3

// Scratch (device globals — allocation-free per harness rules)
__device__ __align__(256) float g_xn[(size_t)MROWS * DMODEL];
__device__ __align__(256) float g_qkvg[(size_t)MROWS * DQKVG];
__device__ __align__(256) float g_og[(size_t)MROWS * DMODEL];
__device__ __align__(256) float g_chunkS[(size_t)BATCHSZ * NHEADS * NCHUNK * 64 * 64];
__device__ __align__(256) float g_state [(size_t)BATCHSZ * NHEADS * NCHUNK * 64 * 64];
__device__ __align__(256) float g_wt [(size_t)DQKVG * KDIM];
__device__ __align__(256) float g_wot[(size_t)DMODEL * KDIM];

// ---------------------------------------------------------------------------
// helpers
// ---------------------------------------------------------------------------
__device__ __forceinline__ uint32_t f2tf32(float x) {
    uint32_t y;
    asm("cvt.rna.tf32.f32 %0, %1;" : "=r"(y) : "f"(x));
    return y;
}
__device__ __forceinline__ float f2tf32f(float x) {
    return __uint_as_float(f2tf32(x));
}
__device__ __forceinline__ uint32_t smem_u32(const void* p) {
    uint32_t a;
    asm("{ .reg .u64 t; cvta.to.shared.u64 t, %1; cvt.u32.u64 %0, t; }" : "=r"(a) : "l"(p));
    return a;
}
__device__ __forceinline__ void mma_tf32(float* d, const uint32_t* a, const uint32_t* b) {
    asm volatile(
        "mma.sync.aligned.m16n8k8.row.col.f32.tf32.tf32.f32 "
        "{%0,%1,%2,%3}, {%4,%5,%6,%7}, {%8,%9}, {%0,%1,%2,%3};\n"
        : "+f"(d[0]), "+f"(d[1]), "+f"(d[2]), "+f"(d[3])
        : "r"(a[0]), "r"(a[1]), "r"(a[2]), "r"(a[3]), "r"(b[0]), "r"(b[1]));
}
// ldmatrix: for tf32 each 8x8 b16 tile = 8 rows x 4 tf32 cols; x4/x2 lane
// distribution matches the HMMA tf32 fragment map exactly.
__device__ __forceinline__ void ldsm_x4(uint32_t* r, uint32_t addr) {
    asm volatile("ldmatrix.sync.aligned.m8n8.x4.shared.b16 {%0,%1,%2,%3}, [%4];"
        : "=r"(r[0]), "=r"(r[1]), "=r"(r[2]), "=r"(r[3]) : "r"(addr));
}
__device__ __forceinline__ void ldsm_x2(uint32_t* r, uint32_t addr) {
    asm volatile("ldmatrix.sync.aligned.m8n8.x2.shared.b16 {%0,%1}, [%2];"
        : "=r"(r[0]), "=r"(r[1]) : "r"(addr));
}
#define CP_ASYNC16(dst, src) \
    asm volatile("cp.async.cg.shared.global [%0], [%1], 16;\n" :: "r"(dst), "l"(src))
#define CP_COMMIT() asm volatile("cp.async.commit_group;\n" ::: "memory")
#define CP_WAIT1()  asm volatile("cp.async.wait_group 1;\n" ::: "memory")

template<int NT> struct GP {
    static constexpr int BN     = NT * 32;
    static constexpr int ABUFW  = 128 * ASTRIDE;
    static constexpr int BBUFW  = BN * ASTRIDE;
    static constexpr int STAGEW = ABUFW + BBUFW;
    static constexpr int SMEMB  = NSTAGE * STAGEW * 4;
};

template<int NT>
__device__ __forceinline__ void issue_stage(const float* __restrict__ Ag,
                                            const float* __restrict__ Bg,
                                            uint32_t sbase, int stage, int k0,
                                            int tid) {
    uint32_t As = sbase + stage * (GP<NT>::STAGEW * 4);
    uint32_t Bs = As + GP<NT>::ABUFW * 4;
    int r0 = tid >> 3, c4 = (tid & 7) * 4;
    #pragma unroll
    for (int i = 0; i < 4; i++) {
        int r = r0 + 32 * i;
        CP_ASYNC16(As + (r * ASTRIDE + c4) * 4, Ag + (size_t)r * KDIM + k0 + c4);
    }
    #pragma unroll
    for (int i = 0; i < GP<NT>::BN / 32; i++) {
        int r = r0 + 32 * i;
        CP_ASYNC16(Bs + (r * ASTRIDE + c4) * 4, Bg + (size_t)r * KDIM + k0 + c4);
    }
}

// fragment loads via ldmatrix:
// A lane addr: row = wm*64 + mt*16 + (lane&15), col words = kk*8 + (lane>>4)*4
// B lane addr: row = wn*(NT*8) + nt*8 + (lane&7), col words = kk*8 + ((lane>>3)&1)*4
template<int NT>
__device__ __forceinline__ void s_compute(uint32_t sAb, uint32_t sBb,
                                          int lane, int wm, int wn,
                                          float acc[4][NT][4]) {
    uint32_t aoff = sAb + (uint32_t)((wm * 64 + (lane & 15)) * ASTRIDE * 4)
                        + (uint32_t)((lane >> 4) * 16);
    uint32_t boff = sBb + (uint32_t)((wn * (NT * 8) + (lane & 7)) * ASTRIDE * 4)
                        + (uint32_t)(((lane >> 3) & 1) * 16);
    #pragma unroll
    for (int kk = 0; kk < 4; kk++) {
        uint32_t a[4][4], b[NT][2];
        #pragma unroll
        for (int mt = 0; mt < 4; mt++)
            ldsm_x4(a[mt], aoff + mt * (16 * ASTRIDE * 4) + kk * 32);
        #pragma unroll
        for (int nt = 0; nt < NT; nt++)
            ldsm_x2(b[nt], boff + nt * (8 * ASTRIDE * 4) + kk * 32);
        #pragma unroll
        for (int mt = 0; mt < 4; mt++)
            #pragma unroll
            for (int nt = 0; nt < NT; nt++)
                mma_tf32(acc[mt][nt], a[mt], b[nt]);
    }
}

// Mainloop, single barrier per k-chunk (R12 hazard analysis holds)
template<int NT>
__device__ __forceinline__ void tf32_mainloop(const float* __restrict__ Ag,
                                              const float* __restrict__ Bg,
                                              uint32_t* sm, int tid,
                                              float acc[4][NT][4]) {
    int lane = tid & 31, warp = tid >> 5;
    int wm = warp & 1, wn = warp >> 1;
    uint32_t sb = smem_u32(sm);

    issue_stage<NT>(Ag, Bg, sb, 0, 0, tid);    CP_COMMIT();
    issue_stage<NT>(Ag, Bg, sb, 1, BK, tid);   CP_COMMIT();

    #pragma unroll 1
    for (int c = 0; c < NKCH; c++) {
        CP_WAIT1();
        __syncthreads();
        int buf = c % NSTAGE;
        uint32_t sAb = sb + buf * (GP<NT>::STAGEW * 4);
        uint32_t sBb = sAb + GP<NT>::ABUFW * 4;
        s_compute<NT>(sAb, sBb, lane, wm, wn, acc);
        if (c + 2 < NKCH)
            issue_stage<NT>(Ag, Bg, sb, (c + 2) % NSTAGE, (c + 2) * BK, tid);
        CP_COMMIT();
    }
}

// ---------------------------------------------------------------------------
// GEMM 1: g_qkvg = g_xn @ g_wt^T + bias (+silu on G block)
// ---------------------------------------------------------------------------
__global__ __launch_bounds__(256, 2)
void tc_gemm_qkvg(const float* __restrict__ bQ, const float* __restrict__ bK,
                  const float* __restrict__ bV, const float* __restrict__ bg) {
    extern __shared__ uint32_t sm[];
    const int NT = 4;
    int tid = threadIdx.x;
    int lane = tid & 31, warp = tid >> 5;
    int wm = warp & 1, wn = warp >> 1;
    int bn = blockIdx.x, bm = blockIdx.y;

    int cb = bn * 128;
    int which = cb >> 10;
    const float* bias;
    if      (which == 0) bias = bQ;
    else if (which == 1) bias = bK;
    else if (which == 2) bias = bV;
    else                 bias = bg;
    const float* Bg = g_wt + (size_t)cb * KDIM;
    const float* Ag = g_xn + (size_t)(bm * 128) * KDIM;

    float acc[4][NT][4];
    #pragma unroll
    for (int i = 0; i < 4; i++)
        #pragma unroll
        for (int j = 0; j < NT; j++)
            #pragma unroll
            for (int k = 0; k < 4; k++) acc[i][j][k] = 0.f;

    tf32_mainloop<NT>(Ag, Bg, sm, tid, acc);

    bool do_silu = (which == 3);
    int row0 = bm * 128 + wm * 64 + (lane >> 2);
    int col0 = cb + wn * 32 + (lane & 3) * 2;
    #pragma unroll
    for (int mt = 0; mt < 4; mt++) {
        #pragma unroll
        for (int nt = 0; nt < NT; nt++) {
            int cg = col0 + nt * 8;
            float b0 = bias[cg & 1023], b1 = bias[(cg + 1) & 1023];
            #pragma unroll
            for (int half = 0; half < 2; half++) {
                size_t row = (size_t)(row0 + mt * 16 + half * 8);
                float v0 = acc[mt][nt][half * 2 + 0] + b0;
                float v1 = acc[mt][nt][half * 2 + 1] + b1;
                if (do_silu) {
                    v0 = v0 / (1.0f + expf(-v0));
                    v1 = v1 / (1.0f + expf(-v1));
                }
                *(float2*)(g_qkvg + row * DQKVG + cg) = make_float2(v0, v1);
            }
        }
    }
}

// ---------------------------------------------------------------------------
// GEMM 2: out = g_og @ g_wot^T + bO + x
// ---------------------------------------------------------------------------
__global__ __launch_bounds__(256, 2)
void tc_gemm_out(const float* __restrict__ bO,
                 const float* __restrict__ x, float* __restrict__ out) {
    extern __shared__ uint32_t sm[];
    const int NT = 4;
    int tid = threadIdx.x;
    int lane = tid & 31, warp = tid >> 5;
    int wm = warp & 1, wn = warp >> 1;
    int bn = blockIdx.x, bm = blockIdx.y;

    int cb = bn * 128;
    const float* Bg = g_wot + (size_t)cb * KDIM;
    const float* Ag = g_og + (size_t)(bm * 128) * KDIM;

    float acc[4][NT][4];
    #pragma unroll
    for (int i = 0; i < 4; i++)
        #pragma unroll
        for (int j = 0; j < NT; j++)
            #pragma unroll
            for (int k = 0; k < 4; k++) acc[i][j][k] = 0.f;

    tf32_mainloop<NT>(Ag, Bg, sm, tid, acc);

    int row0 = bm * 128 + wm * 64 + (lane >> 2);
    int col0 = cb + wn * 32 + (lane & 3) * 2;
    #pragma unroll
    for (int mt = 0; mt < 4; mt++) {
        #pragma unroll
        for (int nt = 0; nt < NT; nt++) {
            int cg = col0 + nt * 8;
            float b0 = bO[cg], b1 = bO[cg + 1];
            #pragma unroll
            for (int half = 0; half < 2; half++) {
                size_t row = (size_t)(row0 + mt * 16 + half * 8);
                float2 xr = *(const float2*)(x + row * DMODEL + cg);
                float2 v;
                v.x = acc[mt][nt][half * 2 + 0] + b0 + xr.x;
                v.y = acc[mt][nt][half * 2 + 1] + b1 + xr.y;
                *(float2*)(out + row * DMODEL + cg) = v;
            }
        }
    }
}

// ---------------------------------------------------------------------------
// prep: fused LayerNorm + weight tf32 pre-round (unchanged)
// ---------------------------------------------------------------------------
__global__ __launch_bounds__(256) void prep_kernel(
    const float* __restrict__ x,
    const float* __restrict__ gamma, const float* __restrict__ beta,
    const float* __restrict__ WQ, const float* __restrict__ WK,
    const float* __restrict__ WV, const float* __restrict__ Wg,
    const float* __restrict__ WO) {
    int blk = blockIdx.x;
    int t = threadIdx.x;
    if (blk < MROWS) {
        const float4* xr = (const float4*)(x + (size_t)blk * DMODEL);
        float4 a = xr[t];
        float s = a.x + a.y + a.z + a.w;
        float q = a.x * a.x + a.y * a.y + a.z * a.z + a.w * a.w;
        #pragma unroll
        for (int o = 16; o > 0; o >>= 1) {
            s += __shfl_xor_sync(0xffffffffu, s, o);
            q += __shfl_xor_sync(0xffffffffu, q, o);
        }
        __shared__ float ss[8], sq[8];
        int w = t >> 5, lane = t & 31;
        if (lane == 0) { ss[w] = s; sq[w] = q; }
        __syncthreads();
        float st = 0.f, qt = 0.f;
        #pragma unroll
        for (int i = 0; i < 8; i++) { st += ss[i]; qt += sq[i]; }
        float mu = st * (1.0f / DMODEL);
        float var = qt * (1.0f / DMODEL) - mu * mu;
        float rs = rsqrtf(var + 1e-5f);
        float4 gm = ((const float4*)gamma)[t];
        float4 bt = ((const float4*)beta)[t];
        float4 o;
        o.x = f2tf32f((a.x - mu) * rs * gm.x + bt.x);
        o.y = f2tf32f((a.y - mu) * rs * gm.y + bt.y);
        o.z = f2tf32f((a.z - mu) * rs * gm.z + bt.z);
        o.w = f2tf32f((a.w - mu) * rs * gm.w + bt.w);
        ((float4*)(g_xn + (size_t)blk * DMODEL))[t] = o;
    } else {
        int i = (blk - MROWS) * 256 + t;
        const float* src;
        float* dst;
        if (i < 1048576) {
            int m = i >> 18;
            int li = i & 262143;
            src = (m == 0 ? WQ : m == 1 ? WK : m == 2 ? WV : Wg) + (size_t)li * 4;
            dst = g_wt + (size_t)i * 4;
        } else {
            int li = i - 1048576;
            src = WO + (size_t)li * 4;
            dst = g_wot + (size_t)li * 4;
        }
        float4 v = *(const float4*)src;
        v.x = f2tf32f(v.x); v.y = f2tf32f(v.y);
        v.z = f2tf32f(v.z); v.w = f2tf32f(v.w);
        *(float4*)dst = v;
    }
}

// ---------------------------------------------------------------------------
// Pass 1: chunk_summary via mma.sync tf32 (unchanged from R13)
// ---------------------------------------------------------------------------
__global__ __launch_bounds__(256) void chunk_summary(const float* __restrict__ alpha_logit) {
    __shared__ float Kts[64 * 68];
    __shared__ float Vt [64 * 68];
    __shared__ float lal[64];

    int c = blockIdx.x & (NCHUNK - 1);
    int h = (blockIdx.x >> 5) & (NHEADS - 1);
    int b = blockIdx.x >> 9;

    int tid = threadIdx.x;
    int lane = tid & 31, wid = tid >> 5;
    int g4 = lane >> 2, q4 = lane & 3;

    if (tid < 64) {
        float a = 1.0f / (1.0f + expf(-alpha_logit[h * 64 + tid]));
        lal[tid] = log2f(a);
    }
    __syncthreads();

    const float* rowb = g_qkvg + ((size_t)(b * TLEN + c * CHUNK)) * DQKVG + h * 64;
    #pragma unroll
    for (int i = 0; i < 4; i++) {
        int idx = tid + i * 256;
        int u = idx >> 4;
        int s4 = (idx & 15) << 2;
        const float* r = rowb + (size_t)u * DQKVG;
        float4 kv = *(const float4*)(r + 1024 + s4);
        float4 vv = *(const float4*)(r + 2048 + s4);
        float e = (float)(63 - u);
        Kts[(s4 + 0) * 68 + u] = kv.x * exp2f(lal[s4 + 0] * e);
        Kts[(s4 + 1) * 68 + u] = kv.y * exp2f(lal[s4 + 1] * e);
        Kts[(s4 + 2) * 68 + u] = kv.z * exp2f(lal[s4 + 2] * e);
        Kts[(s4 + 3) * 68 + u] = kv.w * exp2f(lal[s4 + 3] * e);
        Vt[(s4 + 0) * 68 + u] = vv.x;
        Vt[(s4 + 1) * 68 + u] = vv.y;
        Vt[(s4 + 2) * 68 + u] = vv.z;
        Vt[(s4 + 3) * 68 + u] = vv.w;
    }
    __syncthreads();

    int wm = wid & 1, wn = wid >> 1;
    int moff = wm * 32, noff = wn * 16;
    const uint32_t* Ka = (const uint32_t*)Kts;
    const uint32_t* Vb = (const uint32_t*)Vt;

    float acc[2][2][4];
    #pragma unroll
    for (int i = 0; i < 2; i++)
        #pragma unroll
        for (int j = 0; j < 2; j++)
            #pragma unroll
            for (int k = 0; k < 4; k++) acc[i][j][k] = 0.f;

    #pragma unroll
    for (int kk = 0; kk < 8; kk++) {
        int k0 = kk * 8 + q4;
        uint32_t a[2][4], bf[2][2];
        #pragma unroll
        for (int mt = 0; mt < 2; mt++) {
            int row = moff + mt * 16 + g4;
            a[mt][0] = Ka[row * 68 + k0];
            a[mt][1] = Ka[(row + 8) * 68 + k0];
            a[mt][2] = Ka[row * 68 + k0 + 4];
            a[mt][3] = Ka[(row + 8) * 68 + k0 + 4];
        }
        #pragma unroll
        for (int nt = 0; nt < 2; nt++) {
            int nr = noff + nt * 8 + g4;
            bf[nt][0] = Vb[nr * 68 + k0];
            bf[nt][1] = Vb[nr * 68 + k0 + 4];
        }
        #pragma unroll
        for (int mt = 0; mt < 2; mt++)
            #pragma unroll
            for (int nt = 0; nt < 2; nt++)
                mma_tf32(acc[mt][nt], a[mt], bf[nt]);
    }

    size_t ob = ((size_t)((b * NHEADS + h) * NCHUNK + c)) * 4096;
    #pragma unroll
    for (int mt = 0; mt < 2; mt++)
        #pragma unroll
        for (int nt = 0; nt < 2; nt++)
            #pragma unroll
            for (int half = 0; half < 2; half++) {
                int s = moff + mt * 16 + g4 + half * 8;
                int d = noff + nt * 8 + q4 * 2;
                *(float2*)(g_chunkS + ob + s * 64 + d) =
                    make_float2(acc[mt][nt][half * 2], acc[mt][nt][half * 2 + 1]);
            }
}

// ---------------------------------------------------------------------------
// Pass 2: sequential combine — now 256 blocks (4 per (b,h) plane quarter)
// ---------------------------------------------------------------------------
__global__ __launch_bounds__(256) void chunk_combine(const float* __restrict__ alpha_logit) {
    int bh  = blockIdx.x >> 2;
    int qtr = blockIdx.x & 3;
    int h = bh & (NHEADS - 1);
    int tid = threadIdx.x;
    int idx4 = qtr * 256 + tid;        // float4 index within 4096-elem plane
    int s = idx4 >> 4;

    float a = 1.0f / (1.0f + expf(-alpha_logit[h * 64 + s]));
    float aL = exp2f(log2f(a) * 64.0f);

    float4 H = make_float4(0.f, 0.f, 0.f, 0.f);
    for (int c = 0; c < NCHUNK; c++) {
        size_t base = ((size_t)bh * NCHUNK + c) * 4096;
        ((float4*)(g_state + base))[idx4] = H;
        float4 S = ((const float4*)(g_chunkS + base))[idx4];
        H.x = aL * H.x + S.x;
        H.y = aL * H.y + S.y;
        H.z = aL * H.z + S.z;
        H.w = aL * H.w + S.w;
    }
}

// ---------------------------------------------------------------------------
// Pass 3: chunk_output via mma.sync tf32 (unchanged from R13)
// ---------------------------------------------------------------------------
__global__ __launch_bounds__(256) void chunk_output(const float* __restrict__ alpha_logit) {
    extern __shared__ float smf[];
    float* Qtt = smf;            // [t][s] stride 68
    float* Kst = smf + 4352;     // [u][s] stride 68
    float* Msr = smf + 8704;     // [t][j] stride 132
    float* NNt = smf + 17152;    // [d][j] stride 132

    __shared__ float al[64], lal[64];

    int c = blockIdx.x & (NCHUNK - 1);
    int h = (blockIdx.x >> 5) & (NHEADS - 1);
    int b = blockIdx.x >> 9;

    int tid = threadIdx.x;
    int lane = tid & 31, wid = tid >> 5;
    int g4 = lane >> 2, q4 = lane & 3;

    if (tid < 64) {
        float a = 1.0f / (1.0f + expf(-alpha_logit[h * 64 + tid]));
        al[tid] = a;
        lal[tid] = log2f(a);
    }
    __syncthreads();

    const float* rowb = g_qkvg + ((size_t)(b * TLEN + c * CHUNK)) * DQKVG + h * 64;
    size_t sbase = ((size_t)((b * NHEADS + h) * NCHUNK + c)) * 4096;

    #pragma unroll
    for (int i = 0; i < 4; i++) {
        int idx = tid + i * 256;
        int t = idx >> 4;
        int s4 = (idx & 15) << 2;
        const float* r = rowb + (size_t)t * DQKVG;
        float4 qv = *(const float4*)(r + s4);
        float4 kv = *(const float4*)(r + 1024 + s4);
        float4 vv = *(const float4*)(r + 2048 + s4);
        float tf = (float)t;
        float4 qs;
        qs.x = qv.x * exp2f(lal[s4 + 0] * tf);
        qs.y = qv.y * exp2f(lal[s4 + 1] * tf);
        qs.z = qv.z * exp2f(lal[s4 + 2] * tf);
        qs.w = qv.w * exp2f(lal[s4 + 3] * tf);
        *(float4*)&Qtt[t * 68 + s4] = qs;
        float4 ks;
        ks.x = kv.x * exp2f(-lal[s4 + 0] * tf);
        ks.y = kv.y * exp2f(-lal[s4 + 1] * tf);
        ks.z = kv.z * exp2f(-lal[s4 + 2] * tf);
        ks.w = kv.w * exp2f(-lal[s4 + 3] * tf);
        *(float4*)&Kst[t * 68 + s4] = ks;
        NNt[(s4 + 0) * 132 + t] = vv.x;
        NNt[(s4 + 1) * 132 + t] = vv.y;
        NNt[(s4 + 2) * 132 + t] = vv.z;
        NNt[(s4 + 3) * 132 + t] = vv.w;
        float4 hv = *(const float4*)(g_state + sbase + (size_t)idx * 4);
        NNt[(s4 + 0) * 132 + 64 + t] = hv.x;
        NNt[(s4 + 1) * 132 + 64 + t] = hv.y;
        NNt[(s4 + 2) * 132 + 64 + t] = hv.z;
        NNt[(s4 + 3) * 132 + 64 + t] = hv.w;
    }
    __syncthreads();

    int wm = wid & 1, wn = wid >> 1;
    int moff = wm * 32, noff = wn * 16;
    const uint32_t* Qa = (const uint32_t*)Qtt;
    const uint32_t* Kb = (const uint32_t*)Kst;

    float sc[2][2][4];
    #pragma unroll
    for (int i = 0; i < 2; i++)
        #pragma unroll
        for (int j = 0; j < 2; j++)
            #pragma unroll
            for (int k = 0; k < 4; k++) sc[i][j][k] = 0.f;

    #pragma unroll
    for (int kk = 0; kk < 8; kk++) {
        int k0 = kk * 8 + q4;
        uint32_t a[2][4], bf[2][2];
        #pragma unroll
        for (int mt = 0; mt < 2; mt++) {
            int row = moff + mt * 16 + g4;
            a[mt][0] = Qa[row * 68 + k0];
            a[mt][1] = Qa[(row + 8) * 68 + k0];
            a[mt][2] = Qa[row * 68 + k0 + 4];
            a[mt][3] = Qa[(row + 8) * 68 + k0 + 4];
        }
        #pragma unroll
        for (int nt = 0; nt < 2; nt++) {
            int nr = noff + nt * 8 + g4;
            bf[nt][0] = Kb[nr * 68 + k0];
            bf[nt][1] = Kb[nr * 68 + k0 + 4];
        }
        #pragma unroll
        for (int mt = 0; mt < 2; mt++)
            #pragma unroll
            for (int nt = 0; nt < 2; nt++)
                mma_tf32(sc[mt][nt], a[mt], bf[nt]);
    }

    #pragma unroll
    for (int mt = 0; mt < 2; mt++)
        #pragma unroll
        for (int nt = 0; nt < 2; nt++)
            #pragma unroll
            for (int e = 0; e < 4; e++) {
                int t = moff + mt * 16 + g4 + (e >> 1) * 8;
                int u = noff + nt * 8 + q4 * 2 + (e & 1);
                Msr[t * 132 + u] = (u <= t) ? sc[mt][nt][e] : 0.f;
            }
    #pragma unroll
    for (int i = 0; i < 16; i++) {
        int e = tid + i * 256;
        int t = e >> 6;
        int s = e & 63;
        Msr[t * 132 + 64 + s] = Qtt[t * 68 + s] * al[s];
    }
    __syncthreads();

    const uint32_t* Ma = (const uint32_t*)Msr;
    const uint32_t* Nb = (const uint32_t*)NNt;

    float oc[2][2][4];
    #pragma unroll
    for (int i = 0; i < 2; i++)
        #pragma unroll
        for (int j = 0; j < 2; j++)
            #pragma unroll
            for (int k = 0; k < 4; k++) oc[i][j][k] = 0.f;

    #pragma unroll
    for (int kk = 0; kk < 16; kk++) {
        int k0 = kk * 8 + q4;
        uint32_t a[2][4], bf[2][2];
        #pragma unroll
        for (int mt = 0; mt < 2; mt++) {
            int row = moff + mt * 16 + g4;
            a[mt][0] = Ma[row * 132 + k0];
            a[mt][1] = Ma[(row + 8) * 132 + k0];
            a[mt][2] = Ma[row * 132 + k0 + 4];
            a[mt][3] = Ma[(row + 8) * 132 + k0 + 4];
        }
        #pragma unroll
        for (int nt = 0; nt < 2; nt++) {
            int nr = noff + nt * 8 + g4;
            bf[nt][0] = Nb[nr * 132 + k0];
            bf[nt][1] = Nb[nr * 132 + k0 + 4];
        }
        #pragma unroll
        for (int mt = 0; mt < 2; mt++)
            #pragma unroll
            for (int nt = 0; nt < 2; nt++)
                mma_tf32(oc[mt][nt], a[mt], bf[nt]);
    }

    float* ogb = g_og + ((size_t)(b * TLEN + c * CHUNK)) * DMODEL + h * 64;
    #pragma unroll
    for (int mt = 0; mt < 2; mt++)
        #pragma unroll
        for (int nt = 0; nt < 2; nt++)
            #pragma unroll
            for (int half = 0; half < 2; half++) {
                int t = moff + mt * 16 + g4 + half * 8;
                int d = noff + nt * 8 + q4 * 2;
                float2 g = *(const float2*)(rowb + (size_t)t * DQKVG + 3072 + d);
                float2 ov;
                ov.x = f2tf32f(oc[mt][nt][half * 2 + 0] * g.x);
                ov.y = f2tf32f(oc[mt][nt][half * 2 + 1] * g.y);
                *(float2*)(ogb + (size_t)t * DMODEL + d) = ov;
            }
}

#define CO_SMEM (25600 * 4)   // 102400 bytes

// ---------------------------------------------------------------------------
extern "C" void kernel_launch(void* const* d_in, const int* in_sizes, int n_in,
                              void* d_out, int out_size) {
    const float* x      = (const float*)d_in[0];
    const float* WQ     = (const float*)d_in[1];
    const float* bQ     = (const float*)d_in[2];
    const float* WK     = (const float*)d_in[3];
    const float* bK     = (const float*)d_in[4];
    const float* WV     = (const float*)d_in[5];
    const float* bV     = (const float*)d_in[6];
    const float* WO     = (const float*)d_in[7];
    const float* bO     = (const float*)d_in[8];
    const float* Wg     = (const float*)d_in[9];
    const float* bg     = (const float*)d_in[10];
    const float* alpha  = (const float*)d_in[11];
    const float* gamma  = (const float*)d_in[12];
    const float* beta   = (const float*)d_in[13];
    float* out = (float*)d_out;

    cudaFuncSetAttribute(chunk_output, cudaFuncAttributeMaxDynamicSharedMemorySize, CO_SMEM);
    cudaFuncSetAttribute(tc_gemm_qkvg, cudaFuncAttributeMaxDynamicSharedMemorySize, GP<4>::SMEMB);
    cudaFuncSetAttribute(tc_gemm_out,  cudaFuncAttributeMaxDynamicSharedMemorySize, GP<4>::SMEMB);

    prep_kernel<<<MROWS + 5120, 256>>>(x, gamma, beta, WQ, WK, WV, Wg, WO);

    dim3 g1(DQKVG / 128, MROWS / 128);   // (32, 64)
    tc_gemm_qkvg<<<g1, 256, GP<4>::SMEMB>>>(bQ, bK, bV, bg);

    int nblk = BATCHSZ * NHEADS * NCHUNK;            // 2048
    chunk_summary<<<nblk, 256>>>(alpha);
    chunk_combine<<<BATCHSZ * NHEADS * 4, 256>>>(alpha);
    chunk_output<<<nblk, 256, CO_SMEM>>>(alpha);

    dim3 g2(DMODEL / 128, MROWS / 128);  // (8, 64)
    tc_gemm_out<<<g2, 256, GP<4>::SMEMB>>>(bO, x, out);
}

// round 17
// speedup vs baseline: 1.2586x; 1.0027x over previous
#include <cuda_runtime.h>
#include <math.h>
#include <stdint.h>

// Problem dims
#define MROWS   8192      // B*T
#define DMODEL  1024
#define DQKVG   4096
#define NHEADS  16
#define DHEAD   64
#define TLEN    2048
#define BATCHSZ 4
#define CHUNK   64
#define NCHUNK  (TLEN / CHUNK)   // 32

// mma.sync tf32 GEMM tiling
#define KDIM    1024
#define BK      32
#define NKCH    (KDIM / BK)      // 32
#define ASTRIDE 36               // padded row stride (floats)
#define NSTAGE  3

// Scratch (device globals — allocation-free per harness rules)
__device__ __align__(256) float g_xn[(size_t)MROWS * DMODEL];
__device__ __align__(256) float g_qkvg[(size_t)MROWS * DQKVG];
__device__ __align__(256) float g_og[(size_t)MROWS * DMODEL];
__device__ __align__(256) float g_chunkS[(size_t)BATCHSZ * NHEADS * NCHUNK * 64 * 64];
__device__ __align__(256) float g_state [(size_t)BATCHSZ * NHEADS * NCHUNK * 64 * 64];
__device__ __align__(256) float g_wt [(size_t)DQKVG * KDIM];
__device__ __align__(256) float g_wot[(size_t)DMODEL * KDIM];

// ---------------------------------------------------------------------------
// helpers
// ---------------------------------------------------------------------------
__device__ __forceinline__ uint32_t f2tf32(float x) {
    uint32_t y;
    asm("cvt.rna.tf32.f32 %0, %1;" : "=r"(y) : "f"(x));
    return y;
}
__device__ __forceinline__ float f2tf32f(float x) {
    return __uint_as_float(f2tf32(x));
}
__device__ __forceinline__ uint32_t smem_u32(const void* p) {
    uint32_t a;
    asm("{ .reg .u64 t; cvta.to.shared.u64 t, %1; cvt.u32.u64 %0, t; }" : "=r"(a) : "l"(p));
    return a;
}
__device__ __forceinline__ void mma_tf32(float* d, const uint32_t* a, const uint32_t* b) {
    asm volatile(
        "mma.sync.aligned.m16n8k8.row.col.f32.tf32.tf32.f32 "
        "{%0,%1,%2,%3}, {%4,%5,%6,%7}, {%8,%9}, {%0,%1,%2,%3};\n"
        : "+f"(d[0]), "+f"(d[1]), "+f"(d[2]), "+f"(d[3])
        : "r"(a[0]), "r"(a[1]), "r"(a[2]), "r"(a[3]), "r"(b[0]), "r"(b[1]));
}
__device__ __forceinline__ void ldsm_x4(uint32_t* r, uint32_t addr) {
    asm volatile("ldmatrix.sync.aligned.m8n8.x4.shared.b16 {%0,%1,%2,%3}, [%4];"
        : "=r"(r[0]), "=r"(r[1]), "=r"(r[2]), "=r"(r[3]) : "r"(addr));
}
#define CP_ASYNC16(dst, src) \
    asm volatile("cp.async.cg.shared.global [%0], [%1], 16;\n" :: "r"(dst), "l"(src))
#define CP_COMMIT() asm volatile("cp.async.commit_group;\n" ::: "memory")
#define CP_WAIT1()  asm volatile("cp.async.wait_group 1;\n" ::: "memory")

template<int NT> struct GP {
    static constexpr int BN     = NT * 32;
    static constexpr int ABUFW  = 128 * ASTRIDE;
    static constexpr int BBUFW  = BN * ASTRIDE;
    static constexpr int STAGEW = ABUFW + BBUFW;
    static constexpr int SMEMB  = NSTAGE * STAGEW * 4;
};

template<int NT>
__device__ __forceinline__ void issue_stage(const float* __restrict__ Ag,
                                            const float* __restrict__ Bg,
                                            uint32_t sbase, int stage, int k0,
                                            int tid) {
    uint32_t As = sbase + stage * (GP<NT>::STAGEW * 4);
    uint32_t Bs = As + GP<NT>::ABUFW * 4;
    int r0 = tid >> 3, c4 = (tid & 7) * 4;
    #pragma unroll
    for (int i = 0; i < 4; i++) {
        int r = r0 + 32 * i;
        CP_ASYNC16(As + (r * ASTRIDE + c4) * 4, Ag + (size_t)r * KDIM + k0 + c4);
    }
    #pragma unroll
    for (int i = 0; i < GP<NT>::BN / 32; i++) {
        int r = r0 + 32 * i;
        CP_ASYNC16(Bs + (r * ASTRIDE + c4) * 4, Bg + (size_t)r * KDIM + k0 + c4);
    }
}

// fragment loads via ldmatrix.
// A: per mt one x4 (16 rows x 2 k-halves). lane: row = wm*64+mt*16+(lane&15),
//    khalf = lane>>4.
// B: per PAIR of n-tiles one x4: tile = lane>>3 -> (nt_in_pair = tile>>1,
//    khalf = tile&1); regs {r0,r1} = nt even frag, {r2,r3} = nt odd frag.
template<int NT>
__device__ __forceinline__ void s_compute(uint32_t sAb, uint32_t sBb,
                                          int lane, int wm, int wn,
                                          float acc[4][NT][4]) {
    uint32_t aoff = sAb + (uint32_t)((wm * 64 + (lane & 15)) * ASTRIDE * 4)
                        + (uint32_t)((lane >> 4) * 16);
    int tile = lane >> 3;            // 0..3
    uint32_t boff = sBb
        + (uint32_t)((wn * (NT * 8) + (tile >> 1) * 8 + (lane & 7)) * ASTRIDE * 4)
        + (uint32_t)((tile & 1) * 16);
    #pragma unroll
    for (int kk = 0; kk < 4; kk++) {
        uint32_t a[4][4], bq[NT / 2][4];
        #pragma unroll
        for (int mt = 0; mt < 4; mt++)
            ldsm_x4(a[mt], aoff + mt * (16 * ASTRIDE * 4) + kk * 32);
        #pragma unroll
        for (int p = 0; p < NT / 2; p++)
            ldsm_x4(bq[p], boff + p * (16 * ASTRIDE * 4) + kk * 32);
        #pragma unroll
        for (int mt = 0; mt < 4; mt++)
            #pragma unroll
            for (int nt = 0; nt < NT; nt++)
                mma_tf32(acc[mt][nt], a[mt], bq[nt >> 1] + (nt & 1) * 2);
    }
}

// Mainloop, single barrier per k-chunk (R12 hazard analysis holds)
template<int NT>
__device__ __forceinline__ void tf32_mainloop(const float* __restrict__ Ag,
                                              const float* __restrict__ Bg,
                                              uint32_t* sm, int tid,
                                              float acc[4][NT][4]) {
    int lane = tid & 31, warp = tid >> 5;
    int wm = warp & 1, wn = warp >> 1;
    uint32_t sb = smem_u32(sm);

    issue_stage<NT>(Ag, Bg, sb, 0, 0, tid);    CP_COMMIT();
    issue_stage<NT>(Ag, Bg, sb, 1, BK, tid);   CP_COMMIT();

    #pragma unroll 1
    for (int c = 0; c < NKCH; c++) {
        CP_WAIT1();
        __syncthreads();
        int buf = c % NSTAGE;
        uint32_t sAb = sb + buf * (GP<NT>::STAGEW * 4);
        uint32_t sBb = sAb + GP<NT>::ABUFW * 4;
        s_compute<NT>(sAb, sBb, lane, wm, wn, acc);
        if (c + 2 < NKCH)
            issue_stage<NT>(Ag, Bg, sb, (c + 2) % NSTAGE, (c + 2) * BK, tid);
        CP_COMMIT();
    }
}

// ---------------------------------------------------------------------------
// GEMM 1: g_qkvg = g_xn @ g_wt^T + bias (+silu on G block)
// ---------------------------------------------------------------------------
__global__ __launch_bounds__(256, 2)
void tc_gemm_qkvg(const float* __restrict__ bQ, const float* __restrict__ bK,
                  const float* __restrict__ bV, const float* __restrict__ bg) {
    extern __shared__ uint32_t sm[];
    const int NT = 4;
    int tid = threadIdx.x;
    int lane = tid & 31, warp = tid >> 5;
    int wm = warp & 1, wn = warp >> 1;
    int bn = blockIdx.x, bm = blockIdx.y;

    int cb = bn * 128;
    int which = cb >> 10;
    const float* bias;
    if      (which == 0) bias = bQ;
    else if (which == 1) bias = bK;
    else if (which == 2) bias = bV;
    else                 bias = bg;
    const float* Bg = g_wt + (size_t)cb * KDIM;
    const float* Ag = g_xn + (size_t)(bm * 128) * KDIM;

    float acc[4][NT][4];
    #pragma unroll
    for (int i = 0; i < 4; i++)
        #pragma unroll
        for (int j = 0; j < NT; j++)
            #pragma unroll
            for (int k = 0; k < 4; k++) acc[i][j][k] = 0.f;

    tf32_mainloop<NT>(Ag, Bg, sm, tid, acc);

    bool do_silu = (which == 3);
    int row0 = bm * 128 + wm * 64 + (lane >> 2);
    int col0 = cb + wn * 32 + (lane & 3) * 2;
    #pragma unroll
    for (int mt = 0; mt < 4; mt++) {
        #pragma unroll
        for (int nt = 0; nt < NT; nt++) {
            int cg = col0 + nt * 8;
            float b0 = bias[cg & 1023], b1 = bias[(cg + 1) & 1023];
            #pragma unroll
            for (int half = 0; half < 2; half++) {
                size_t row = (size_t)(row0 + mt * 16 + half * 8);
                float v0 = acc[mt][nt][half * 2 + 0] + b0;
                float v1 = acc[mt][nt][half * 2 + 1] + b1;
                if (do_silu) {
                    v0 = v0 / (1.0f + expf(-v0));
                    v1 = v1 / (1.0f + expf(-v1));
                }
                *(float2*)(g_qkvg + row * DQKVG + cg) = make_float2(v0, v1);
            }
        }
    }
}

// ---------------------------------------------------------------------------
// GEMM 2: out = g_og @ g_wot^T + bO + x
// ---------------------------------------------------------------------------
__global__ __launch_bounds__(256, 2)
void tc_gemm_out(const float* __restrict__ bO,
                 const float* __restrict__ x, float* __restrict__ out) {
    extern __shared__ uint32_t sm[];
    const int NT = 4;
    int tid = threadIdx.x;
    int lane = tid & 31, warp = tid >> 5;
    int wm = warp & 1, wn = warp >> 1;
    int bn = blockIdx.x, bm = blockIdx.y;

    int cb = bn * 128;
    const float* Bg = g_wot + (size_t)cb * KDIM;
    const float* Ag = g_og + (size_t)(bm * 128) * KDIM;

    float acc[4][NT][4];
    #pragma unroll
    for (int i = 0; i < 4; i++)
        #pragma unroll
        for (int j = 0; j < NT; j++)
            #pragma unroll
            for (int k = 0; k < 4; k++) acc[i][j][k] = 0.f;

    tf32_mainloop<NT>(Ag, Bg, sm, tid, acc);

    int row0 = bm * 128 + wm * 64 + (lane >> 2);
    int col0 = cb + wn * 32 + (lane & 3) * 2;
    #pragma unroll
    for (int mt = 0; mt < 4; mt++) {
        #pragma unroll
        for (int nt = 0; nt < NT; nt++) {
            int cg = col0 + nt * 8;
            float b0 = bO[cg], b1 = bO[cg + 1];
            #pragma unroll
            for (int half = 0; half < 2; half++) {
                size_t row = (size_t)(row0 + mt * 16 + half * 8);
                float2 xr = *(const float2*)(x + row * DMODEL + cg);
                float2 v;
                v.x = acc[mt][nt][half * 2 + 0] + b0 + xr.x;
                v.y = acc[mt][nt][half * 2 + 1] + b1 + xr.y;
                *(float2*)(out + row * DMODEL + cg) = v;
            }
        }
    }
}

// ---------------------------------------------------------------------------
// prep: fused LayerNorm + weight tf32 pre-round (unchanged)
// ---------------------------------------------------------------------------
__global__ __launch_bounds__(256) void prep_kernel(
    const float* __restrict__ x,
    const float* __restrict__ gamma, const float* __restrict__ beta,
    const float* __restrict__ WQ, const float* __restrict__ WK,
    const float* __restrict__ WV, const float* __restrict__ Wg,
    const float* __restrict__ WO) {
    int blk = blockIdx.x;
    int t = threadIdx.x;
    if (blk < MROWS) {
        const float4* xr = (const float4*)(x + (size_t)blk * DMODEL);
        float4 a = xr[t];
        float s = a.x + a.y + a.z + a.w;
        float q = a.x * a.x + a.y * a.y + a.z * a.z + a.w * a.w;
        #pragma unroll
        for (int o = 16; o > 0; o >>= 1) {
            s += __shfl_xor_sync(0xffffffffu, s, o);
            q += __shfl_xor_sync(0xffffffffu, q, o);
        }
        __shared__ float ss[8], sq[8];
        int w = t >> 5, lane = t & 31;
        if (lane == 0) { ss[w] = s; sq[w] = q; }
        __syncthreads();
        float st = 0.f, qt = 0.f;
        #pragma unroll
        for (int i = 0; i < 8; i++) { st += ss[i]; qt += sq[i]; }
        float mu = st * (1.0f / DMODEL);
        float var = qt * (1.0f / DMODEL) - mu * mu;
        float rs = rsqrtf(var + 1e-5f);
        float4 gm = ((const float4*)gamma)[t];
        float4 bt = ((const float4*)beta)[t];
        float4 o;
        o.x = f2tf32f((a.x - mu) * rs * gm.x + bt.x);
        o.y = f2tf32f((a.y - mu) * rs * gm.y + bt.y);
        o.z = f2tf32f((a.z - mu) * rs * gm.z + bt.z);
        o.w = f2tf32f((a.w - mu) * rs * gm.w + bt.w);
        ((float4*)(g_xn + (size_t)blk * DMODEL))[t] = o;
    } else {
        int i = (blk - MROWS) * 256 + t;
        const float* src;
        float* dst;
        if (i < 1048576) {
            int m = i >> 18;
            int li = i & 262143;
            src = (m == 0 ? WQ : m == 1 ? WK : m == 2 ? WV : Wg) + (size_t)li * 4;
            dst = g_wt + (size_t)i * 4;
        } else {
            int li = i - 1048576;
            src = WO + (size_t)li * 4;
            dst = g_wot + (size_t)li * 4;
        }
        float4 v = *(const float4*)src;
        v.x = f2tf32f(v.x); v.y = f2tf32f(v.y);
        v.z = f2tf32f(v.z); v.w = f2tf32f(v.w);
        *(float4*)dst = v;
    }
}

// ---------------------------------------------------------------------------
// Pass 1: chunk_summary via mma.sync tf32; decay powers from smem tables
// ---------------------------------------------------------------------------
__global__ __launch_bounds__(256) void chunk_summary(const float* __restrict__ alpha_logit) {
    __shared__ float Kts[64 * 68];
    __shared__ float Vt [64 * 68];
    __shared__ float A1t[64][8], A8t[64][8];

    int c = blockIdx.x & (NCHUNK - 1);
    int h = (blockIdx.x >> 5) & (NHEADS - 1);
    int b = blockIdx.x >> 9;

    int tid = threadIdx.x;
    int lane = tid & 31, wid = tid >> 5;
    int g4 = lane >> 2, q4 = lane & 3;

    if (tid < 64) {
        float a = 1.0f / (1.0f + expf(-alpha_logit[h * 64 + tid]));
        float p = 1.f;
        #pragma unroll
        for (int k = 0; k < 8; k++) { A1t[tid][k] = p; p *= a; }   // p = a^8
        float q = 1.f;
        #pragma unroll
        for (int k = 0; k < 8; k++) { A8t[tid][k] = q; q *= p; }
    }
    __syncthreads();

    const float* rowb = g_qkvg + ((size_t)(b * TLEN + c * CHUNK)) * DQKVG + h * 64;
    {
        int u0 = tid >> 4;                  // 0..15
        int s4 = (tid & 15) << 2;
        float pw[4], stp[4];
        #pragma unroll
        for (int j = 0; j < 4; j++) {
            int s = s4 + j;
            int e3 = 15 - u0;               // exponent at i=3
            pw[j]  = A8t[s][e3 >> 3] * A1t[s][e3 & 7];
            stp[j] = A8t[s][2];             // a^16
        }
        #pragma unroll
        for (int i = 3; i >= 0; i--) {      // e = 63-u grows as i decreases
            int u = u0 + 16 * i;
            const float* r = rowb + (size_t)u * DQKVG;
            float4 kv = *(const float4*)(r + 1024 + s4);
            float4 vv = *(const float4*)(r + 2048 + s4);
            Kts[(s4 + 0) * 68 + u] = kv.x * pw[0];
            Kts[(s4 + 1) * 68 + u] = kv.y * pw[1];
            Kts[(s4 + 2) * 68 + u] = kv.z * pw[2];
            Kts[(s4 + 3) * 68 + u] = kv.w * pw[3];
            Vt[(s4 + 0) * 68 + u] = vv.x;
            Vt[(s4 + 1) * 68 + u] = vv.y;
            Vt[(s4 + 2) * 68 + u] = vv.z;
            Vt[(s4 + 3) * 68 + u] = vv.w;
            if (i > 0) {
                #pragma unroll
                for (int j = 0; j < 4; j++) pw[j] *= stp[j];
            }
        }
    }
    __syncthreads();

    int wm = wid & 1, wn = wid >> 1;
    int moff = wm * 32, noff = wn * 16;
    const uint32_t* Ka = (const uint32_t*)Kts;
    const uint32_t* Vb = (const uint32_t*)Vt;

    float acc[2][2][4];
    #pragma unroll
    for (int i = 0; i < 2; i++)
        #pragma unroll
        for (int j = 0; j < 2; j++)
            #pragma unroll
            for (int k = 0; k < 4; k++) acc[i][j][k] = 0.f;

    #pragma unroll
    for (int kk = 0; kk < 8; kk++) {
        int k0 = kk * 8 + q4;
        uint32_t a[2][4], bf[2][2];
        #pragma unroll
        for (int mt = 0; mt < 2; mt++) {
            int row = moff + mt * 16 + g4;
            a[mt][0] = Ka[row * 68 + k0];
            a[mt][1] = Ka[(row + 8) * 68 + k0];
            a[mt][2] = Ka[row * 68 + k0 + 4];
            a[mt][3] = Ka[(row + 8) * 68 + k0 + 4];
        }
        #pragma unroll
        for (int nt = 0; nt < 2; nt++) {
            int nr = noff + nt * 8 + g4;
            bf[nt][0] = Vb[nr * 68 + k0];
            bf[nt][1] = Vb[nr * 68 + k0 + 4];
        }
        #pragma unroll
        for (int mt = 0; mt < 2; mt++)
            #pragma unroll
            for (int nt = 0; nt < 2; nt++)
                mma_tf32(acc[mt][nt], a[mt], bf[nt]);
    }

    size_t ob = ((size_t)((b * NHEADS + h) * NCHUNK + c)) * 4096;
    #pragma unroll
    for (int mt = 0; mt < 2; mt++)
        #pragma unroll
        for (int nt = 0; nt < 2; nt++)
            #pragma unroll
            for (int half = 0; half < 2; half++) {
                int s = moff + mt * 16 + g4 + half * 8;
                int d = noff + nt * 8 + q4 * 2;
                *(float2*)(g_chunkS + ob + s * 64 + d) =
                    make_float2(acc[mt][nt][half * 2], acc[mt][nt][half * 2 + 1]);
            }
}

// ---------------------------------------------------------------------------
// Pass 2: sequential combine — 256 blocks, software-pipelined S prefetch
// ---------------------------------------------------------------------------
__global__ __launch_bounds__(256) void chunk_combine(const float* __restrict__ alpha_logit) {
    int bh  = blockIdx.x >> 2;
    int qtr = blockIdx.x & 3;
    int h = bh & (NHEADS - 1);
    int tid = threadIdx.x;
    int idx4 = qtr * 256 + tid;
    int s = idx4 >> 4;

    float a = 1.0f / (1.0f + expf(-alpha_logit[h * 64 + s]));
    // a^64 via 6 squarings (exact chain, no exp/log)
    float aL = a;
    #pragma unroll
    for (int i = 0; i < 6; i++) aL = aL * aL;

    size_t base0 = ((size_t)bh * NCHUNK) * 4096;
    float4 H = make_float4(0.f, 0.f, 0.f, 0.f);
    float4 S = ((const float4*)(g_chunkS + base0))[idx4];
    for (int c = 0; c < NCHUNK; c++) {
        size_t base = base0 + (size_t)c * 4096;
        ((float4*)(g_state + base))[idx4] = H;
        float4 Sn;
        if (c + 1 < NCHUNK)
            Sn = ((const float4*)(g_chunkS + base + 4096))[idx4];
        H.x = aL * H.x + S.x;
        H.y = aL * H.y + S.y;
        H.z = aL * H.z + S.z;
        H.w = aL * H.w + S.w;
        S = Sn;
    }
}

// ---------------------------------------------------------------------------
// Pass 3: chunk_output via mma.sync tf32; decay powers from smem tables
// ---------------------------------------------------------------------------
__global__ __launch_bounds__(256) void chunk_output(const float* __restrict__ alpha_logit) {
    extern __shared__ float smf[];
    float* Qtt = smf;            // [t][s] stride 68
    float* Kst = smf + 4352;     // [u][s] stride 68
    float* Msr = smf + 8704;     // [t][j] stride 132
    float* NNt = smf + 17152;    // [d][j] stride 132

    __shared__ float al[64];
    __shared__ float A1t[64][8], A8t[64][8], B1t[64][8], B8t[64][8];

    int c = blockIdx.x & (NCHUNK - 1);
    int h = (blockIdx.x >> 5) & (NHEADS - 1);
    int b = blockIdx.x >> 9;

    int tid = threadIdx.x;
    int lane = tid & 31, wid = tid >> 5;
    int g4 = lane >> 2, q4 = lane & 3;

    if (tid < 64) {
        float a = 1.0f / (1.0f + expf(-alpha_logit[h * 64 + tid]));
        al[tid] = a;
        float p = 1.f;
        #pragma unroll
        for (int k = 0; k < 8; k++) { A1t[tid][k] = p; p *= a; }   // p = a^8
        float q = 1.f;
        #pragma unroll
        for (int k = 0; k < 8; k++) { A8t[tid][k] = q; q *= p; }
        float bb = 1.0f / a;
        float pb = 1.f;
        #pragma unroll
        for (int k = 0; k < 8; k++) { B1t[tid][k] = pb; pb *= bb; } // pb = b^8
        float qb = 1.f;
        #pragma unroll
        for (int k = 0; k < 8; k++) { B8t[tid][k] = qb; qb *= pb; }
    }
    __syncthreads();

    const float* rowb = g_qkvg + ((size_t)(b * TLEN + c * CHUNK)) * DQKVG + h * 64;
    size_t sbase = ((size_t)((b * NHEADS + h) * NCHUNK + c)) * 4096;

    {
        int t0 = tid >> 4;                 // 0..15
        int s4 = (tid & 15) << 2;
        float pA[4], sA[4], pB[4], sB[4];
        #pragma unroll
        for (int j = 0; j < 4; j++) {
            int s = s4 + j;
            pA[j] = A8t[s][t0 >> 3] * A1t[s][t0 & 7];   // a^t0
            sA[j] = A8t[s][2];                           // a^16
            pB[j] = B8t[s][t0 >> 3] * B1t[s][t0 & 7];   // a^-t0
            sB[j] = B8t[s][2];                           // a^-16
        }
        #pragma unroll
        for (int i = 0; i < 4; i++) {
            int idx = tid + i * 256;
            int t = t0 + 16 * i;
            const float* r = rowb + (size_t)t * DQKVG;
            float4 qv = *(const float4*)(r + s4);
            float4 kv = *(const float4*)(r + 1024 + s4);
            float4 vv = *(const float4*)(r + 2048 + s4);
            Qtt[t * 68 + s4 + 0] = qv.x * pA[0];
            Qtt[t * 68 + s4 + 1] = qv.y * pA[1];
            Qtt[t * 68 + s4 + 2] = qv.z * pA[2];
            Qtt[t * 68 + s4 + 3] = qv.w * pA[3];
            Kst[t * 68 + s4 + 0] = kv.x * pB[0];
            Kst[t * 68 + s4 + 1] = kv.y * pB[1];
            Kst[t * 68 + s4 + 2] = kv.z * pB[2];
            Kst[t * 68 + s4 + 3] = kv.w * pB[3];
            NNt[(s4 + 0) * 132 + t] = vv.x;
            NNt[(s4 + 1) * 132 + t] = vv.y;
            NNt[(s4 + 2) * 132 + t] = vv.z;
            NNt[(s4 + 3) * 132 + t] = vv.w;
            float4 hv = *(const float4*)(g_state + sbase + (size_t)idx * 4);
            NNt[(s4 + 0) * 132 + 64 + t] = hv.x;
            NNt[(s4 + 1) * 132 + 64 + t] = hv.y;
            NNt[(s4 + 2) * 132 + 64 + t] = hv.z;
            NNt[(s4 + 3) * 132 + 64 + t] = hv.w;
            if (i < 3) {
                #pragma unroll
                for (int j = 0; j < 4; j++) { pA[j] *= sA[j]; pB[j] *= sB[j]; }
            }
        }
    }
    __syncthreads();

    int wm = wid & 1, wn = wid >> 1;
    int moff = wm * 32, noff = wn * 16;
    const uint32_t* Qa = (const uint32_t*)Qtt;
    const uint32_t* Kb = (const uint32_t*)Kst;

    float sc[2][2][4];
    #pragma unroll
    for (int i = 0; i < 2; i++)
        #pragma unroll
        for (int j = 0; j < 2; j++)
            #pragma unroll
            for (int k = 0; k < 4; k++) sc[i][j][k] = 0.f;

    #pragma unroll
    for (int kk = 0; kk < 8; kk++) {
        int k0 = kk * 8 + q4;
        uint32_t a[2][4], bf[2][2];
        #pragma unroll
        for (int mt = 0; mt < 2; mt++) {
            int row = moff + mt * 16 + g4;
            a[mt][0] = Qa[row * 68 + k0];
            a[mt][1] = Qa[(row + 8) * 68 + k0];
            a[mt][2] = Qa[row * 68 + k0 + 4];
            a[mt][3] = Qa[(row + 8) * 68 + k0 + 4];
        }
        #pragma unroll
        for (int nt = 0; nt < 2; nt++) {
            int nr = noff + nt * 8 + g4;
            bf[nt][0] = Kb[nr * 68 + k0];
            bf[nt][1] = Kb[nr * 68 + k0 + 4];
        }
        #pragma unroll
        for (int mt = 0; mt < 2; mt++)
            #pragma unroll
            for (int nt = 0; nt < 2; nt++)
                mma_tf32(sc[mt][nt], a[mt], bf[nt]);
    }

    #pragma unroll
    for (int mt = 0; mt < 2; mt++)
        #pragma unroll
        for (int nt = 0; nt < 2; nt++)
            #pragma unroll
            for (int e = 0; e < 4; e++) {
                int t = moff + mt * 16 + g4 + (e >> 1) * 8;
                int u = noff + nt * 8 + q4 * 2 + (e & 1);
                Msr[t * 132 + u] = (u <= t) ? sc[mt][nt][e] : 0.f;
            }
    #pragma unroll
    for (int i = 0; i < 16; i++) {
        int e = tid + i * 256;
        int t = e >> 6;
        int s = e & 63;
        Msr[t * 132 + 64 + s] = Qtt[t * 68 + s] * al[s];
    }
    __syncthreads();

    const uint32_t* Ma = (const uint32_t*)Msr;
    const uint32_t* Nb = (const uint32_t*)NNt;

    float oc[2][2][4];
    #pragma unroll
    for (int i = 0; i < 2; i++)
        #pragma unroll
        for (int j = 0; j < 2; j++)
            #pragma unroll
            for (int k = 0; k < 4; k++) oc[i][j][k] = 0.f;

    #pragma unroll
    for (int kk = 0; kk < 16; kk++) {
        int k0 = kk * 8 + q4;
        uint32_t a[2][4], bf[2][2];
        #pragma unroll
        for (int mt = 0; mt < 2; mt++) {
            int row = moff + mt * 16 + g4;
            a[mt][0] = Ma[row * 132 + k0];
            a[mt][1] = Ma[(row + 8) * 132 + k0];
            a[mt][2] = Ma[row * 132 + k0 + 4];
            a[mt][3] = Ma[(row + 8) * 132 + k0 + 4];
        }
        #pragma unroll
        for (int nt = 0; nt < 2; nt++) {
            int nr = noff + nt * 8 + g4;
            bf[nt][0] = Nb[nr * 132 + k0];
            bf[nt][1] = Nb[nr * 132 + k0 + 4];
        }
        #pragma unroll
        for (int mt = 0; mt < 2; mt++)
            #pragma unroll
            for (int nt = 0; nt < 2; nt++)
                mma_tf32(oc[mt][nt], a[mt], bf[nt]);
    }

    float* ogb = g_og + ((size_t)(b * TLEN + c * CHUNK)) * DMODEL + h * 64;
    #pragma unroll
    for (int mt = 0; mt < 2; mt++)
        #pragma unroll
        for (int nt = 0; nt < 2; nt++)
            #pragma unroll
            for (int half = 0; half < 2; half++) {
                int t = moff + mt * 16 + g4 + half * 8;
                int d = noff + nt * 8 + q4 * 2;
                float2 g = *(const float2*)(rowb + (size_t)t * DQKVG + 3072 + d);
                float2 ov;
                ov.x = f2tf32f(oc[mt][nt][half * 2 + 0] * g.x);
                ov.y = f2tf32f(oc[mt][nt][half * 2 + 1] * g.y);
                *(float2*)(ogb + (size_t)t * DMODEL + d) = ov;
            }
}

#define CO_SMEM (25600 * 4)   // 102400 bytes dynamic

// ---------------------------------------------------------------------------
extern "C" void kernel_launch(void* const* d_in, const int* in_sizes, int n_in,
                              void* d_out, int out_size) {
    const float* x      = (const float*)d_in[0];
    const float* WQ     = (const float*)d_in[1];
    const float* bQ     = (const float*)d_in[2];
    const float* WK     = (const float*)d_in[3];
    const float* bK     = (const float*)d_in[4];
    const float* WV     = (const float*)d_in[5];
    const float* bV     = (const float*)d_in[6];
    const float* WO     = (const float*)d_in[7];
    const float* bO     = (const float*)d_in[8];
    const float* Wg     = (const float*)d_in[9];
    const float* bg     = (const float*)d_in[10];
    const float* alpha  = (const float*)d_in[11];
    const float* gamma  = (const float*)d_in[12];
    const float* beta   = (const float*)d_in[13];
    float* out = (float*)d_out;

    cudaFuncSetAttribute(chunk_output, cudaFuncAttributeMaxDynamicSharedMemorySize, CO_SMEM);
    cudaFuncSetAttribute(tc_gemm_qkvg, cudaFuncAttributeMaxDynamicSharedMemorySize, GP<4>::SMEMB);
    cudaFuncSetAttribute(tc_gemm_out,  cudaFuncAttributeMaxDynamicSharedMemorySize, GP<4>::SMEMB);

    prep_kernel<<<MROWS + 5120, 256>>>(x, gamma, beta, WQ, WK, WV, Wg, WO);

    dim3 g1(DQKVG / 128, MROWS / 128);   // (32, 64)
    tc_gemm_qkvg<<<g1, 256, GP<4>::SMEMB>>>(bQ, bK, bV, bg);

    int nblk = BATCHSZ * NHEADS * NCHUNK;            // 2048
    chunk_summary<<<nblk, 256>>>(alpha);
    chunk_combine<<<BATCHSZ * NHEADS * 4, 256>>>(alpha);
    chunk_output<<<nblk, 256, CO_SMEM>>>(alpha);

    dim3 g2(DMODEL / 128, MROWS / 128);  // (8, 64)
    tc_gemm_out<<<g2, 256, GP<4>::SMEMB>>>(bO, x, out);
}